// round 1
// baseline (speedup 1.0000x reference)
#include <cuda_runtime.h>
#include <cstdint>

#define EPSB 1e-5f

static constexpr int B_   = 2;
static constexpr int N_   = 250000;
static constexpr int P_   = B_ * N_;          // 500000
static constexpr int G_   = 64;
static constexpr int NS_  = B_ * G_ * G_ * G_; // 524288
static constexpr int OUT_ = 64;
static constexpr int TP   = 32;               // points per block
static constexpr int NBLK = P_ / TP;          // 15625

// ---------------- folded-weight scratch (device globals: no allocation) ----
__device__ float g_W0f[3 * 64];
__device__ float g_b0f[64];
__device__ float g_W1f[64 * 128];
__device__ float g_b1f[128];
__device__ float g_W2f[128 * 256];
__device__ float g_b2f[256];

using ull = unsigned long long;

// ---------------- packed f32x2 helpers (sm_103a FFMA2 path) ---------------
__device__ __forceinline__ ull pack2(float x, float y) {
    ull r; asm("mov.b64 %0, {%1, %2};" : "=l"(r) : "f"(x), "f"(y)); return r;
}
__device__ __forceinline__ float2 unpack2(ull v) {
    float2 r; asm("mov.b64 {%0, %1}, %2;" : "=f"(r.x), "=f"(r.y) : "l"(v)); return r;
}
__device__ __forceinline__ void ffma2(ull& d, ull a, ull b) {
    asm("fma.rn.f32x2 %0, %1, %2, %0;" : "+l"(d) : "l"(a), "l"(b));
}

// order-preserving float -> uint encode (for atomicMax on floats incl. negatives)
__device__ __forceinline__ unsigned encf(float f) {
    unsigned u = __float_as_uint(f);
    return (u & 0x80000000u) ? ~u : (u | 0x80000000u);
}
__device__ __forceinline__ unsigned decf(unsigned u) {
    if (u == 0u) return 0u;  // untouched voxel -> 0.0f (bits 0)
    unsigned b = (u & 0x80000000u) ? (u & 0x7FFFFFFFu) : ~u;
    return b;
}

// ---------------- BN folding precompute ------------------------------------
__global__ void fold_kernel(
    const float* __restrict__ bn0g, const float* __restrict__ bn0b,
    const float* __restrict__ bn0m, const float* __restrict__ bn0v,
    const float* __restrict__ bn1g, const float* __restrict__ bn1b,
    const float* __restrict__ bn1m, const float* __restrict__ bn1v,
    const float* __restrict__ bn2g, const float* __restrict__ bn2b,
    const float* __restrict__ bn2m, const float* __restrict__ bn2v,
    const float* __restrict__ bn3g, const float* __restrict__ bn3b,
    const float* __restrict__ bn3m, const float* __restrict__ bn3v,
    const float* __restrict__ W0, const float* __restrict__ b0,
    const float* __restrict__ W1, const float* __restrict__ b1,
    const float* __restrict__ W2, const float* __restrict__ b2)
{
    const int t = threadIdx.x;

    // W0f[i][j] = s0[i] * W0[i][j] * s1[j]
    for (int idx = t; idx < 3 * 64; idx += 256) {
        int i = idx / 64, j = idx % 64;
        float s0 = bn0g[i] * rsqrtf(bn0v[i] + EPSB);
        float s1 = bn1g[j] * rsqrtf(bn1v[j] + EPSB);
        g_W0f[idx] = s0 * W0[idx] * s1;
    }
    // b0f[j] = s1[j]*( sum_i c0[i]*W0[i][j] + b0[j] - m1[j] ) + bb1[j]
    for (int j = t; j < 64; j += 256) {
        float s1 = bn1g[j] * rsqrtf(bn1v[j] + EPSB);
        float sum = 0.f;
        for (int i = 0; i < 3; i++) {
            float s0 = bn0g[i] * rsqrtf(bn0v[i] + EPSB);
            float c0 = bn0b[i] - bn0m[i] * s0;
            sum += c0 * W0[i * 64 + j];
        }
        g_b0f[j] = s1 * (sum + b0[j] - bn1m[j]) + bn1b[j];
    }
    // layer1: W1f = W1 * s2[col];  b1f = s2*(b1 - m2) + bb2
    for (int idx = t; idx < 64 * 128; idx += 256) {
        int j = idx & 127;
        float s2 = bn2g[j] * rsqrtf(bn2v[j] + EPSB);
        g_W1f[idx] = W1[idx] * s2;
    }
    for (int j = t; j < 128; j += 256) {
        float s2 = bn2g[j] * rsqrtf(bn2v[j] + EPSB);
        g_b1f[j] = s2 * (b1[j] - bn2m[j]) + bn2b[j];
    }
    // layer2: W2f = W2 * s3[col];  b2f = s3*(b2 - m3) + bb3
    for (int idx = t; idx < 128 * 256; idx += 256) {
        int j = idx & 255;
        float s3 = bn3g[j] * rsqrtf(bn3v[j] + EPSB);
        g_W2f[idx] = W2[idx] * s3;
    }
    for (int j = t; j < 256; j += 256) {
        float s3 = bn3g[j] * rsqrtf(bn3v[j] + EPSB);
        g_b2f[j] = s3 * (b2[j] - bn3m[j]) + bn3b[j];
    }
}

// ---------------- output init / decode -------------------------------------
__global__ void init_kernel(uint4* __restrict__ o, int n4) {
    int i = blockIdx.x * 256 + threadIdx.x;
    if (i < n4) o[i] = make_uint4(0u, 0u, 0u, 0u);
}
__global__ void decode_kernel(uint4* __restrict__ o, int n4) {
    int i = blockIdx.x * 256 + threadIdx.x;
    if (i < n4) {
        uint4 v = o[i];
        v.x = decf(v.x); v.y = decf(v.y); v.z = decf(v.z); v.w = decf(v.w);
        o[i] = v;
    }
}

// ---------------- generic fp32x2 layer (SMEM staged) ------------------------
// act layout: sIn[k*33 + pt], k in [0,Cin), pt in [0,32)
// thread mapping: pg = tid&7 -> points {pg, pg+8, pg+16, pg+24}
//                 cg = tid>>3 -> channels [cg*CPT, cg*CPT+CPT)
template<int Cin, int Cout, bool RELU>
__device__ __forceinline__ void run_layer(
    const float* __restrict__ gW, const float* __restrict__ gB,
    const float* sIn, float* sOut, float* sW, int tid)
{
    const int pg = tid & 7, cg = tid >> 3;
    constexpr int CPT = Cout / 32;   // channels per thread
    constexpr int Q2  = CPT / 2;     // f32x2 accumulators per point

    ull acc[4][Q2];
    #pragma unroll
    for (int q2 = 0; q2 < Q2; q2++) {
        float bx = gB[cg * CPT + 2 * q2];
        float by = gB[cg * CPT + 2 * q2 + 1];
        ull bb = pack2(bx, by);
        #pragma unroll
        for (int r = 0; r < 4; r++) acc[r][q2] = bb;
    }

    #pragma unroll 1
    for (int k0 = 0; k0 < Cin; k0 += 32) {
        __syncthreads();   // prior chunk consumed / prior layer's stores visible
        {   // stage weight chunk: rows [k0,k0+32) x Cout, coalesced float4
            const float4* src = (const float4*)(gW + k0 * Cout);
            float4* dst = (float4*)sW;
            #pragma unroll
            for (int j = 0; j < CPT; j++) dst[tid + 256 * j] = src[tid + 256 * j];
        }
        __syncthreads();
        #pragma unroll
        for (int kk = 0; kk < 32; kk++) {
            const float* arow = sIn + (k0 + kk) * 33;
            ull aa[4];
            #pragma unroll
            for (int r = 0; r < 4; r++) { float a = arow[pg + 8 * r]; aa[r] = pack2(a, a); }
            const ull* wv = (const ull*)(sW + kk * Cout + cg * CPT);
            #pragma unroll
            for (int q2 = 0; q2 < Q2; q2++) {
                ull w = wv[q2];
                #pragma unroll
                for (int r = 0; r < 4; r++) ffma2(acc[r][q2], aa[r], w);
            }
        }
    }

    #pragma unroll
    for (int q2 = 0; q2 < Q2; q2++) {
        #pragma unroll
        for (int r = 0; r < 4; r++) {
            float2 v = unpack2(acc[r][q2]);
            if (RELU) { v.x = fmaxf(v.x, 0.f); v.y = fmaxf(v.y, 0.f); }
            int ch = cg * CPT + 2 * q2, pt = pg + 8 * r;
            sOut[ch * 33 + pt]       = v.x;
            sOut[(ch + 1) * 33 + pt] = v.y;
        }
    }
}

// ---------------- fused MLP + voxel max-scatter -----------------------------
__global__ void __launch_bounds__(256, 2) mlp_scatter_kernel(
    const float* __restrict__ pt_fea, const int* __restrict__ pt_ind,
    const float* __restrict__ W3, const float* __restrict__ b3,
    unsigned* __restrict__ out)
{
    extern __shared__ float smem[];
    float* buf1 = smem;                  // 8448 floats (up to 256 ch x 33)
    float* buf2 = buf1 + 8448;           // 8448 floats
    float* sW   = buf2 + 8448;           // 8192 floats (32 x 256 chunk)
    float* sX   = sW + 8192;             // 96 floats (32 pts x 3)
    int*   sSeg = (int*)(sX + 96);       // 32 ints

    const int tid = threadIdx.x;
    const int blk = blockIdx.x;

    if (tid < 96) sX[tid] = pt_fea[blk * 96 + tid];
    if (tid < TP) {
        int p  = blk * TP + tid;
        int ix = pt_ind[3 * p + 0];
        int iy = pt_ind[3 * p + 1];
        int iz = pt_ind[3 * p + 2];
        int bb = (p >= N_) ? 1 : 0;
        sSeg[tid] = ((bb * G_ + iz) * G_ + iy) * G_ + ix;  // (b, z, y, x)
    }
    __syncthreads();

    // layer 0: 3 -> 64 (BN0+Lin0+BN1 folded), relu, write buf2
    {
        const int pg = tid & 7, cg = tid >> 3;  // ch = cg*2 + q
        float acc[4][2];
        #pragma unroll
        for (int q = 0; q < 2; q++) {
            float b = g_b0f[cg * 2 + q];
            #pragma unroll
            for (int r = 0; r < 4; r++) acc[r][q] = b;
        }
        #pragma unroll
        for (int i = 0; i < 3; i++) {
            float w0 = g_W0f[i * 64 + cg * 2];
            float w1 = g_W0f[i * 64 + cg * 2 + 1];
            #pragma unroll
            for (int r = 0; r < 4; r++) {
                float a = sX[(pg + 8 * r) * 3 + i];
                acc[r][0] = fmaf(a, w0, acc[r][0]);
                acc[r][1] = fmaf(a, w1, acc[r][1]);
            }
        }
        #pragma unroll
        for (int r = 0; r < 4; r++) {
            int pt = pg + 8 * r;
            buf2[(cg * 2 + 0) * 33 + pt] = fmaxf(acc[r][0], 0.f);
            buf2[(cg * 2 + 1) * 33 + pt] = fmaxf(acc[r][1], 0.f);
        }
    }

    run_layer< 64, 128, true >(g_W1f, g_b1f, buf2, buf1, sW, tid);
    run_layer<128, 256, true >(g_W2f, g_b2f, buf1, buf2, sW, tid);
    run_layer<256,  64, false>(W3,    b3,    buf2, buf1, sW, tid);
    __syncthreads();

    // scatter-max: 32 pts x 64 ch; lanes cover consecutive channels -> coalesced RED
    #pragma unroll
    for (int it = 0; it < (TP * 64) / 256; it++) {
        int idx = tid + it * 256;
        int p = idx >> 6, ch = idx & 63;
        unsigned e = encf(buf1[ch * 33 + p]);
        atomicMax(out + ((unsigned)sSeg[p] * 64u + (unsigned)ch), e);
    }
}

// ---------------- launcher ---------------------------------------------------
extern "C" void kernel_launch(void* const* d_in, const int* in_sizes, int n_in,
                              void* d_out, int out_size)
{
    const float* pt_fea = (const float*)d_in[0];
    const int*   pt_ind = (const int*)  d_in[1];
    const float *bn0g = (const float*)d_in[2],  *bn0b = (const float*)d_in[3],
                *bn0m = (const float*)d_in[4],  *bn0v = (const float*)d_in[5];
    const float *bn1g = (const float*)d_in[6],  *bn1b = (const float*)d_in[7],
                *bn1m = (const float*)d_in[8],  *bn1v = (const float*)d_in[9];
    const float *bn2g = (const float*)d_in[10], *bn2b = (const float*)d_in[11],
                *bn2m = (const float*)d_in[12], *bn2v = (const float*)d_in[13];
    const float *bn3g = (const float*)d_in[14], *bn3b = (const float*)d_in[15],
                *bn3m = (const float*)d_in[16], *bn3v = (const float*)d_in[17];
    const float *W0 = (const float*)d_in[18], *b0 = (const float*)d_in[19];
    const float *W1 = (const float*)d_in[20], *b1 = (const float*)d_in[21];
    const float *W2 = (const float*)d_in[22], *b2 = (const float*)d_in[23];
    const float *W3 = (const float*)d_in[24], *b3 = (const float*)d_in[25];

    const int SMEM_BYTES = (8448 * 2 + 8192 + 96 + 32) * 4;  // 100864
    cudaFuncSetAttribute(mlp_scatter_kernel,
                         cudaFuncAttributeMaxDynamicSharedMemorySize, SMEM_BYTES);

    fold_kernel<<<1, 256>>>(bn0g, bn0b, bn0m, bn0v, bn1g, bn1b, bn1m, bn1v,
                            bn2g, bn2b, bn2m, bn2v, bn3g, bn3b, bn3m, bn3v,
                            W0, b0, W1, b1, W2, b2);

    const int n4 = NS_ * OUT_ / 4;  // 8388608 uint4
    init_kernel<<<(n4 + 255) / 256, 256>>>((uint4*)d_out, n4);

    mlp_scatter_kernel<<<NBLK, 256, SMEM_BYTES>>>(pt_fea, pt_ind, W3, b3,
                                                  (unsigned*)d_out);

    decode_kernel<<<(n4 + 255) / 256, 256>>>((uint4*)d_out, n4);
}

// round 3
// speedup vs baseline: 2.1285x; 2.1285x over previous
#include <cuda_runtime.h>
#include <cuda_bf16.h>
#include <cstdint>

#define EPSB 1e-5f

static constexpr int B_   = 2;
static constexpr int N_   = 250000;
static constexpr int P_   = B_ * N_;            // 500000
static constexpr int G_   = 64;
static constexpr int NS_  = B_ * G_ * G_ * G_;  // 524288
static constexpr int OUT_ = 64;
static constexpr int TIL  = 128;
static constexpr int NT_CTA = (P_ + TIL - 1) / TIL;  // 3907

// ---------------- device scratch (no allocation) ---------------------------
__device__ float g_W0f[3 * 64];
__device__ float g_b0f[64];
__device__ float g_b1f[128];
__device__ float g_b2f[256];
// folded, transposed [n][k], hi/lo bf16 split, SW128 pre-swizzled, sliced
__device__ __align__(16) unsigned char g_Wt1[32768];   // 1 slice: [128n][64k] hi+lo
__device__ __align__(16) unsigned char g_Wt2[131072];  // 4 slices (g*2+kc): [128n][64k] hi+lo
__device__ __align__(16) unsigned char g_Wt3[65536];   // 4 slices (kc): [64n][64k] hi+lo

__host__ __device__ __forceinline__ uint32_t sw128(uint32_t o) {
    return o ^ ((o >> 3) & 0x70u);
}

// ---------------- helpers ----------------------------------------------------
__device__ __forceinline__ uint32_t smem_u32(const void* p) {
    uint32_t a;
    asm("{ .reg .u64 t; cvta.to.shared.u64 t, %1; cvt.u32.u64 %0, t; }"
        : "=r"(a) : "l"(p));
    return a;
}
__device__ __forceinline__ void ldsm_x4(uint32_t& r0, uint32_t& r1,
                                        uint32_t& r2, uint32_t& r3, uint32_t addr) {
    asm volatile("ldmatrix.sync.aligned.m8n8.x4.shared.b16 {%0,%1,%2,%3}, [%4];"
                 : "=r"(r0), "=r"(r1), "=r"(r2), "=r"(r3) : "r"(addr));
}
__device__ __forceinline__ void mma_bf16(float (&c)[4], const uint32_t (&a)[4],
                                         const uint32_t (&b)[2]) {
    asm volatile("mma.sync.aligned.m16n8k16.row.col.f32.bf16.bf16.f32 "
                 "{%0,%1,%2,%3}, {%4,%5,%6,%7}, {%8,%9}, {%0,%1,%2,%3};"
                 : "+f"(c[0]), "+f"(c[1]), "+f"(c[2]), "+f"(c[3])
                 : "r"(a[0]), "r"(a[1]), "r"(a[2]), "r"(a[3]), "r"(b[0]), "r"(b[1]));
}
// pack two f32 -> bf16x2 word: v0 -> bits[15:0], v1 -> bits[31:16]
__device__ __forceinline__ uint32_t pack2bf(float v0, float v1) {
    uint32_t r;
    asm("cvt.rn.bf16x2.f32 %0, %1, %2;" : "=r"(r) : "f"(v1), "f"(v0));
    return r;
}
__device__ __forceinline__ float bf_lo(uint32_t w) { return __uint_as_float(w << 16); }
__device__ __forceinline__ float bf_hi(uint32_t w) { return __uint_as_float(w & 0xFFFF0000u); }

__device__ __forceinline__ unsigned encf(float f) {
    unsigned u = __float_as_uint(f);
    return (u & 0x80000000u) ? ~u : (u | 0x80000000u);
}
__device__ __forceinline__ unsigned decf(unsigned u) {
    if (u == 0u) return 0u;
    return (u & 0x80000000u) ? (u & 0x7FFFFFFFu) : ~u;
}

// ---------------- BN folding + weight transform -----------------------------
__global__ void fold_kernel(
    const float* __restrict__ bn0g, const float* __restrict__ bn0b,
    const float* __restrict__ bn0m, const float* __restrict__ bn0v,
    const float* __restrict__ bn1g, const float* __restrict__ bn1b,
    const float* __restrict__ bn1m, const float* __restrict__ bn1v,
    const float* __restrict__ bn2g, const float* __restrict__ bn2b,
    const float* __restrict__ bn2m, const float* __restrict__ bn2v,
    const float* __restrict__ bn3g, const float* __restrict__ bn3b,
    const float* __restrict__ bn3m, const float* __restrict__ bn3v,
    const float* __restrict__ W0, const float* __restrict__ b0,
    const float* __restrict__ W1, const float* __restrict__ b1,
    const float* __restrict__ W2, const float* __restrict__ b2,
    const float* __restrict__ W3)
{
    const int t = threadIdx.x;

    for (int idx = t; idx < 3 * 64; idx += 256) {
        int i = idx / 64, j = idx % 64;
        float s0 = bn0g[i] * rsqrtf(bn0v[i] + EPSB);
        float s1 = bn1g[j] * rsqrtf(bn1v[j] + EPSB);
        g_W0f[idx] = s0 * W0[idx] * s1;
    }
    for (int j = t; j < 64; j += 256) {
        float s1 = bn1g[j] * rsqrtf(bn1v[j] + EPSB);
        float sum = 0.f;
        for (int i = 0; i < 3; i++) {
            float s0 = bn0g[i] * rsqrtf(bn0v[i] + EPSB);
            float c0 = bn0b[i] - bn0m[i] * s0;
            sum += c0 * W0[i * 64 + j];
        }
        g_b0f[j] = s1 * (sum + b0[j] - bn1m[j]) + bn1b[j];
    }

    // L1: [128n][64k] hi+lo, sw128
    for (int idx = t; idx < 128 * 64; idx += 256) {
        int n = idx >> 6, k = idx & 63;
        float s2 = bn2g[n] * rsqrtf(bn2v[n] + EPSB);
        float w = W1[k * 128 + n] * s2;
        __nv_bfloat16 hi = __float2bfloat16(w);
        __nv_bfloat16 lo = __float2bfloat16(w - __bfloat162float(hi));
        uint32_t off = sw128((uint32_t)(n * 128 + k * 2));
        *(__nv_bfloat16*)(g_Wt1 + off)         = hi;
        *(__nv_bfloat16*)(g_Wt1 + 16384 + off) = lo;
    }
    for (int n = t; n < 128; n += 256) {
        float s2 = bn2g[n] * rsqrtf(bn2v[n] + EPSB);
        g_b1f[n] = s2 * (b1[n] - bn2m[n]) + bn2b[n];
    }

    // L2: slice (g*2+kc) of 32KB each
    for (int idx = t; idx < 256 * 128; idx += 256) {
        int n = idx >> 7, k = idx & 127;
        float s3 = bn3g[n] * rsqrtf(bn3v[n] + EPSB);
        float w = W2[k * 256 + n] * s3;
        __nv_bfloat16 hi = __float2bfloat16(w);
        __nv_bfloat16 lo = __float2bfloat16(w - __bfloat162float(hi));
        int g = n >> 7, kc = k >> 6, nl = n & 127, kl = k & 63;
        uint32_t base = (uint32_t)(g * 2 + kc) * 32768u;
        uint32_t off  = sw128((uint32_t)(nl * 128 + kl * 2));
        *(__nv_bfloat16*)(g_Wt2 + base + off)         = hi;
        *(__nv_bfloat16*)(g_Wt2 + base + 16384 + off) = lo;
    }
    for (int n = t; n < 256; n += 256) {
        float s3 = bn3g[n] * rsqrtf(bn3v[n] + EPSB);
        g_b2f[n] = s3 * (b2[n] - bn3m[n]) + bn3b[n];
    }

    // L3: slice (kc) of 16KB each: [64n][64k] hi(8K)+lo(8K)
    for (int idx = t; idx < 64 * 256; idx += 256) {
        int n = idx / 256, k = idx % 256;
        float w = W3[k * 64 + n];
        __nv_bfloat16 hi = __float2bfloat16(w);
        __nv_bfloat16 lo = __float2bfloat16(w - __bfloat162float(hi));
        int kc = k >> 6, kl = k & 63;
        uint32_t base = (uint32_t)kc * 16384u;
        uint32_t off  = sw128((uint32_t)(n * 128 + kl * 2));
        *(__nv_bfloat16*)(g_Wt3 + base + off)        = hi;
        *(__nv_bfloat16*)(g_Wt3 + base + 8192 + off) = lo;
    }
}

// ---------------- output init / decode -------------------------------------
__global__ void init_kernel(uint4* __restrict__ o, int n4) {
    int i = blockIdx.x * 256 + threadIdx.x;
    if (i < n4) o[i] = make_uint4(0u, 0u, 0u, 0u);
}
__global__ void decode_kernel(uint4* __restrict__ o, int n4) {
    int i = blockIdx.x * 256 + threadIdx.x;
    if (i < n4) {
        uint4 v = o[i];
        v.x = decf(v.x); v.y = decf(v.y); v.z = decf(v.z); v.w = decf(v.w);
        o[i] = v;
    }
}

// ---------------- SMEM layout ------------------------------------------------
// 6 act chunk-pairs (32KB each: hi 16KB + lo 16KB), weight buffer 32KB, misc.
__host__ __device__ constexpr uint32_t SLOT(int i) { return (uint32_t)i * 32768u; }
static constexpr uint32_t WBUF = 196608;
static constexpr uint32_t MISC = 229376;                 // sBias(1024) + sSeg(512)
static constexpr uint32_t SMEM_TOTAL = 230912;

__device__ __forceinline__ void stageW(const unsigned char* g, unsigned char* s,
                                       int bytes, int tid) {
    const float4* src = (const float4*)g;
    float4* dst = (float4*)s;
    int n = bytes >> 4;
    for (int i = tid; i < n; i += 256) dst[i] = src[i];
}

// ---------------- warp GEMM over one 64-K chunk ------------------------------
// warp tile: m32 x (NT*8) cols; acc[2][NT][4]; 3-pass hi/lo interleaved per k-step
template<int NT>
__device__ __forceinline__ void mma_kchunk(
    float (&acc)[2][NT][4],
    uint32_t aHi, uint32_t aLo,   // act chunk base + wm*32*128
    uint32_t bHi, uint32_t bLo,   // weight slice base + n0*128
    int lane)
{
    const int rA  = (lane & 7) + ((lane >> 3) & 1) * 8;
    const int kA8 = ((lane >> 4) & 1) * 8;
    const uint32_t xorA = (uint32_t)((rA & 7) << 4);
    const int rB  = (lane & 7) + ((lane >> 4) & 1) * 8;
    const int kB8 = ((lane >> 3) & 1) * 8;
    const uint32_t xorB = (uint32_t)((lane & 7) << 4);

    #pragma unroll
    for (int ks = 0; ks < 4; ks++) {
        const int k0 = ks * 16;
        uint32_t ah[2][4], al[2][4];
        #pragma unroll
        for (int mt = 0; mt < 2; mt++) {
            uint32_t off = (uint32_t)((mt * 16 + rA) * 128)
                         + (((uint32_t)(k0 + kA8) << 1) ^ xorA);
            ldsm_x4(ah[mt][0], ah[mt][1], ah[mt][2], ah[mt][3], aHi + off);
            ldsm_x4(al[mt][0], al[mt][1], al[mt][2], al[mt][3], aLo + off);
        }
        uint32_t bh[NT][2], bl[NT][2];
        #pragma unroll
        for (int q = 0; q < NT / 2; q++) {
            uint32_t off = (uint32_t)((q * 16 + rB) * 128)
                         + (((uint32_t)(k0 + kB8) << 1) ^ xorB);
            ldsm_x4(bh[2*q][0], bh[2*q][1], bh[2*q+1][0], bh[2*q+1][1], bHi + off);
            ldsm_x4(bl[2*q][0], bl[2*q][1], bl[2*q+1][0], bl[2*q+1][1], bLo + off);
        }
        #pragma unroll
        for (int mt = 0; mt < 2; mt++)
            #pragma unroll
            for (int nt = 0; nt < NT; nt++) {
                mma_bf16(acc[mt][nt], ah[mt], bh[nt]);
                mma_bf16(acc[mt][nt], ah[mt], bl[nt]);
                mma_bf16(acc[mt][nt], al[mt], bh[nt]);
            }
    }
}

// hidden-layer epilogue: acc -> bias -> relu -> hi/lo bf16 -> act chunk (64 cols)
template<int NT>
__device__ __forceinline__ void epi_hidden(
    float (&acc)[2][NT][4], unsigned char* smem, uint32_t outOff,
    const float* sBias, int colBase, int wm, int lane)
{
    const int r0 = lane >> 2;
    #pragma unroll
    for (int mt = 0; mt < 2; mt++) {
        int row1 = wm * 32 + mt * 16 + r0;
        int row2 = row1 + 8;
        #pragma unroll
        for (int nt = 0; nt < NT; nt++) {
            int kl = nt * 8 + (lane & 3) * 2;
            float bi0 = sBias[colBase + kl], bi1 = sBias[colBase + kl + 1];
            {
                float v0 = fmaxf(acc[mt][nt][0] + bi0, 0.f);
                float v1 = fmaxf(acc[mt][nt][1] + bi1, 0.f);
                uint32_t h = pack2bf(v0, v1);
                uint32_t l = pack2bf(v0 - bf_lo(h), v1 - bf_hi(h));
                uint32_t off = (uint32_t)(row1 * 128)
                             + (((uint32_t)kl << 1) ^ ((uint32_t)(row1 & 7) << 4));
                *(uint32_t*)(smem + outOff + off)         = h;
                *(uint32_t*)(smem + outOff + 16384 + off) = l;
            }
            {
                float v0 = fmaxf(acc[mt][nt][2] + bi0, 0.f);
                float v1 = fmaxf(acc[mt][nt][3] + bi1, 0.f);
                uint32_t h = pack2bf(v0, v1);
                uint32_t l = pack2bf(v0 - bf_lo(h), v1 - bf_hi(h));
                uint32_t off = (uint32_t)(row2 * 128)
                             + (((uint32_t)kl << 1) ^ ((uint32_t)(row2 & 7) << 4));
                *(uint32_t*)(smem + outOff + off)         = h;
                *(uint32_t*)(smem + outOff + 16384 + off) = l;
            }
        }
    }
}

// ---------------- fused MLP + scatter ----------------------------------------
__global__ void __launch_bounds__(256, 1) mlp_kernel(
    const float* __restrict__ pt_fea, const int* __restrict__ pt_ind,
    const float* __restrict__ b3, unsigned* __restrict__ out)
{
    extern __shared__ __align__(1024) unsigned char smem[];
    float* sBias = (float*)(smem + MISC);
    int*   sSeg  = (int*)(smem + MISC + 1024);
    const uint32_t sb = smem_u32(smem);

    const int tid = threadIdx.x, wid = tid >> 5, lane = tid & 31;
    const int wm = wid & 3, wn = wid >> 2;
    const int blk = blockIdx.x;

    // segment ids
    if (tid < 128) {
        int gp = blk * 128 + tid;
        if (gp < P_) {
            int ix = pt_ind[3 * gp], iy = pt_ind[3 * gp + 1], iz = pt_ind[3 * gp + 2];
            int bb = (gp >= N_) ? 1 : 0;
            sSeg[tid] = ((bb * G_ + iz) * G_ + iy) * G_ + ix;
        } else sSeg[tid] = -1;
    }

    // ---- L0: 3 -> 64 scalar fp32, hi/lo split into slot 0 ----
    {
        int p = tid >> 1, j0 = (tid & 1) * 32;
        int gp = blk * 128 + p;
        float x0 = 0.f, x1 = 0.f, x2 = 0.f;
        if (gp < P_) { x0 = pt_fea[gp*3]; x1 = pt_fea[gp*3+1]; x2 = pt_fea[gp*3+2]; }
        #pragma unroll
        for (int j = 0; j < 32; j += 2) {
            int k = j0 + j;
            float v0 = g_b0f[k]   + x0*g_W0f[k]   + x1*g_W0f[64+k]   + x2*g_W0f[128+k];
            float v1 = g_b0f[k+1] + x0*g_W0f[k+1] + x1*g_W0f[64+k+1] + x2*g_W0f[128+k+1];
            v0 = fmaxf(v0, 0.f); v1 = fmaxf(v1, 0.f);
            uint32_t h = pack2bf(v0, v1);
            uint32_t l = pack2bf(v0 - bf_lo(h), v1 - bf_hi(h));
            uint32_t off = sw128((uint32_t)(p * 128 + k * 2));
            *(uint32_t*)(smem + SLOT(0) + off)         = h;
            *(uint32_t*)(smem + SLOT(0) + 16384 + off) = l;
        }
    }

    const uint32_t aWm = (uint32_t)(wm * 32 * 128);

    // ---- L1: 64 -> 128, in slot0, out slots 1,2 ----
    __syncthreads();
    stageW(g_Wt1, smem + WBUF, 32768, tid);
    if (tid < 128) sBias[tid] = g_b1f[tid];
    __syncthreads();
    {
        float acc[2][8][4];
        #pragma unroll
        for (int a = 0; a < 2; a++)
            #pragma unroll
            for (int b = 0; b < 8; b++)
                #pragma unroll
                for (int c = 0; c < 4; c++) acc[a][b][c] = 0.f;
        uint32_t bOff = (uint32_t)(wn * 64 * 128);
        mma_kchunk<8>(acc, sb + SLOT(0) + aWm, sb + SLOT(0) + 16384 + aWm,
                      sb + WBUF + bOff, sb + WBUF + 16384 + bOff, lane);
        epi_hidden<8>(acc, smem, SLOT(1 + wn), sBias, wn * 64, wm, lane);
    }

    // ---- L2: 128 -> 256, in slots 1,2, out slots {3,4,5,0} ----
    const int outSlot[4] = {3, 4, 5, 0};
    for (int g = 0; g < 2; g++) {
        float acc[2][8][4];
        #pragma unroll
        for (int a = 0; a < 2; a++)
            #pragma unroll
            for (int b = 0; b < 8; b++)
                #pragma unroll
                for (int c = 0; c < 4; c++) acc[a][b][c] = 0.f;
        for (int kc = 0; kc < 2; kc++) {
            __syncthreads();
            stageW(g_Wt2 + (uint32_t)(g * 2 + kc) * 32768u, smem + WBUF, 32768, tid);
            if (g == 0 && kc == 0) sBias[tid] = g_b2f[tid];
            __syncthreads();
            uint32_t bOff = (uint32_t)(wn * 64 * 128);
            mma_kchunk<8>(acc, sb + SLOT(1 + kc) + aWm, sb + SLOT(1 + kc) + 16384 + aWm,
                          sb + WBUF + bOff, sb + WBUF + 16384 + bOff, lane);
        }
        int gc = g * 2 + wn;                    // global 64-col chunk index
        epi_hidden<8>(acc, smem, SLOT(outSlot[gc]), sBias, g * 128 + wn * 64, wm, lane);
    }

    // ---- L3: 256 -> 64, in slots {3,4,5,0}, out -> atomics ----
    {
        float acc[2][4][4];
        #pragma unroll
        for (int a = 0; a < 2; a++)
            #pragma unroll
            for (int b = 0; b < 4; b++)
                #pragma unroll
                for (int c = 0; c < 4; c++) acc[a][b][c] = 0.f;
        for (int kc = 0; kc < 4; kc++) {
            __syncthreads();
            stageW(g_Wt3 + (uint32_t)kc * 16384u, smem + WBUF, 16384, tid);
            if (kc == 0 && tid < 64) sBias[tid] = b3[tid];
            __syncthreads();
            uint32_t aBase = SLOT(outSlot[kc]);
            uint32_t bOff = (uint32_t)(wn * 32 * 128);
            mma_kchunk<4>(acc, sb + aBase + aWm, sb + aBase + 16384 + aWm,
                          sb + WBUF + bOff, sb + WBUF + 8192 + bOff, lane);
        }
        // scatter-max
        const int r0 = lane >> 2;
        #pragma unroll
        for (int mt = 0; mt < 2; mt++) {
            int row1 = wm * 32 + mt * 16 + r0;
            int row2 = row1 + 8;
            int seg1 = sSeg[row1], seg2 = sSeg[row2];
            #pragma unroll
            for (int nt = 0; nt < 4; nt++) {
                int col = wn * 32 + nt * 8 + (lane & 3) * 2;
                float bi0 = sBias[col], bi1 = sBias[col + 1];
                if (seg1 >= 0) {
                    unsigned base = (unsigned)seg1 * 64u + (unsigned)col;
                    atomicMax(out + base,     encf(acc[mt][nt][0] + bi0));
                    atomicMax(out + base + 1, encf(acc[mt][nt][1] + bi1));
                }
                if (seg2 >= 0) {
                    unsigned base = (unsigned)seg2 * 64u + (unsigned)col;
                    atomicMax(out + base,     encf(acc[mt][nt][2] + bi0));
                    atomicMax(out + base + 1, encf(acc[mt][nt][3] + bi1));
                }
            }
        }
    }
}

// ---------------- launcher ---------------------------------------------------
extern "C" void kernel_launch(void* const* d_in, const int* in_sizes, int n_in,
                              void* d_out, int out_size)
{
    const float* pt_fea = (const float*)d_in[0];
    const int*   pt_ind = (const int*)  d_in[1];
    const float *bn0g = (const float*)d_in[2],  *bn0b = (const float*)d_in[3],
                *bn0m = (const float*)d_in[4],  *bn0v = (const float*)d_in[5];
    const float *bn1g = (const float*)d_in[6],  *bn1b = (const float*)d_in[7],
                *bn1m = (const float*)d_in[8],  *bn1v = (const float*)d_in[9];
    const float *bn2g = (const float*)d_in[10], *bn2b = (const float*)d_in[11],
                *bn2m = (const float*)d_in[12], *bn2v = (const float*)d_in[13];
    const float *bn3g = (const float*)d_in[14], *bn3b = (const float*)d_in[15],
                *bn3m = (const float*)d_in[16], *bn3v = (const float*)d_in[17];
    const float *W0 = (const float*)d_in[18], *b0 = (const float*)d_in[19];
    const float *W1 = (const float*)d_in[20], *b1 = (const float*)d_in[21];
    const float *W2 = (const float*)d_in[22], *b2 = (const float*)d_in[23];
    const float *W3 = (const float*)d_in[24], *b3 = (const float*)d_in[25];

    cudaFuncSetAttribute(mlp_kernel, cudaFuncAttributeMaxDynamicSharedMemorySize,
                         SMEM_TOTAL);

    fold_kernel<<<1, 256>>>(bn0g, bn0b, bn0m, bn0v, bn1g, bn1b, bn1m, bn1v,
                            bn2g, bn2b, bn2m, bn2v, bn3g, bn3b, bn3m, bn3v,
                            W0, b0, W1, b1, W2, b2, W3);

    const int n4 = NS_ * OUT_ / 4;
    init_kernel<<<(n4 + 255) / 256, 256>>>((uint4*)d_out, n4);

    mlp_kernel<<<NT_CTA, 256, SMEM_TOTAL>>>(pt_fea, pt_ind, b3, (unsigned*)d_out);

    decode_kernel<<<(n4 + 255) / 256, 256>>>((uint4*)d_out, n4);
}

// round 4
// speedup vs baseline: 2.2932x; 1.0774x over previous
#include <cuda_runtime.h>
#include <cuda_fp16.h>
#include <cstdint>

#define EPSB 1e-5f

static constexpr int B_   = 2;
static constexpr int N_   = 250000;
static constexpr int P_   = B_ * N_;            // 500000
static constexpr int G_   = 64;
static constexpr int NS_  = B_ * G_ * G_ * G_;  // 524288
static constexpr int OUT_ = 64;
static constexpr int TIL  = 128;
static constexpr int NT_CTA = (P_ + TIL - 1) / TIL;  // 3907

// ---------------- device scratch (no allocation) ---------------------------
__device__ float g_W0f[3 * 64];
__device__ float g_b0f[64];
__device__ float g_b1f[128];
__device__ float g_b2f[256];
// folded, transposed [n][k], single fp16, SW128 pre-swizzled, sliced
__device__ __align__(16) unsigned char g_Wh1[16384];   // [128n][64k]
__device__ __align__(16) unsigned char g_Wh2[65536];   // 4 x 16KB slices (g*2+kc)
__device__ __align__(16) unsigned char g_Wh3[32768];   // 4 x 8KB slices (kc): [64n][64k]

__host__ __device__ __forceinline__ uint32_t sw128(uint32_t o) {
    return o ^ ((o >> 3) & 0x70u);
}

// ---------------- helpers ----------------------------------------------------
__device__ __forceinline__ uint32_t smem_u32(const void* p) {
    uint32_t a;
    asm("{ .reg .u64 t; cvta.to.shared.u64 t, %1; cvt.u32.u64 %0, t; }"
        : "=r"(a) : "l"(p));
    return a;
}
__device__ __forceinline__ void ldsm_x4(uint32_t& r0, uint32_t& r1,
                                        uint32_t& r2, uint32_t& r3, uint32_t addr) {
    asm volatile("ldmatrix.sync.aligned.m8n8.x4.shared.b16 {%0,%1,%2,%3}, [%4];"
                 : "=r"(r0), "=r"(r1), "=r"(r2), "=r"(r3) : "r"(addr));
}
__device__ __forceinline__ void mma_f16(float (&c)[4], const uint32_t (&a)[4],
                                        const uint32_t (&b)[2]) {
    asm volatile("mma.sync.aligned.m16n8k16.row.col.f32.f16.f16.f32 "
                 "{%0,%1,%2,%3}, {%4,%5,%6,%7}, {%8,%9}, {%0,%1,%2,%3};"
                 : "+f"(c[0]), "+f"(c[1]), "+f"(c[2]), "+f"(c[3])
                 : "r"(a[0]), "r"(a[1]), "r"(a[2]), "r"(a[3]), "r"(b[0]), "r"(b[1]));
}
// pack two f32 -> f16x2 word: v0 -> bits[15:0], v1 -> bits[31:16]
__device__ __forceinline__ uint32_t pack2h(float v0, float v1) {
    uint32_t r;
    asm("cvt.rn.f16x2.f32 %0, %1, %2;" : "=r"(r) : "f"(v1), "f"(v0));
    return r;
}
__device__ __forceinline__ float h_lo(uint32_t w) {
    return __half2float(__ushort_as_half((unsigned short)(w & 0xFFFFu)));
}
__device__ __forceinline__ float h_hi(uint32_t w) {
    return __half2float(__ushort_as_half((unsigned short)(w >> 16)));
}

__device__ __forceinline__ unsigned encf(float f) {
    unsigned u = __float_as_uint(f);
    return (u & 0x80000000u) ? ~u : (u | 0x80000000u);
}
__device__ __forceinline__ unsigned decf(unsigned u) {
    if (u == 0u) return 0u;
    return (u & 0x80000000u) ? (u & 0x7FFFFFFFu) : ~u;
}

// cp.async staging
__device__ __forceinline__ void stage_async(uint32_t sdst, const unsigned char* g,
                                            int bytes, int tid) {
    for (int i = tid * 16; i < bytes; i += 256 * 16)
        asm volatile("cp.async.cg.shared.global [%0], [%1], 16;"
                     :: "r"(sdst + (uint32_t)i), "l"(g + i));
}
#define CP_COMMIT() asm volatile("cp.async.commit_group;" ::: "memory")
#define CP_WAIT0()  asm volatile("cp.async.wait_group 0;" ::: "memory")

// ---------------- BN folding + weight transform -----------------------------
__global__ void fold_kernel(
    const float* __restrict__ bn0g, const float* __restrict__ bn0b,
    const float* __restrict__ bn0m, const float* __restrict__ bn0v,
    const float* __restrict__ bn1g, const float* __restrict__ bn1b,
    const float* __restrict__ bn1m, const float* __restrict__ bn1v,
    const float* __restrict__ bn2g, const float* __restrict__ bn2b,
    const float* __restrict__ bn2m, const float* __restrict__ bn2v,
    const float* __restrict__ bn3g, const float* __restrict__ bn3b,
    const float* __restrict__ bn3m, const float* __restrict__ bn3v,
    const float* __restrict__ W0, const float* __restrict__ b0,
    const float* __restrict__ W1, const float* __restrict__ b1,
    const float* __restrict__ W2, const float* __restrict__ b2,
    const float* __restrict__ W3)
{
    const int t = threadIdx.x;

    for (int idx = t; idx < 3 * 64; idx += 256) {
        int i = idx / 64, j = idx % 64;
        float s0 = bn0g[i] * rsqrtf(bn0v[i] + EPSB);
        float s1 = bn1g[j] * rsqrtf(bn1v[j] + EPSB);
        g_W0f[idx] = s0 * W0[idx] * s1;
    }
    for (int j = t; j < 64; j += 256) {
        float s1 = bn1g[j] * rsqrtf(bn1v[j] + EPSB);
        float sum = 0.f;
        for (int i = 0; i < 3; i++) {
            float s0 = bn0g[i] * rsqrtf(bn0v[i] + EPSB);
            float c0 = bn0b[i] - bn0m[i] * s0;
            sum += c0 * W0[i * 64 + j];
        }
        g_b0f[j] = s1 * (sum + b0[j] - bn1m[j]) + bn1b[j];
    }

    // L1: [128n][64k] fp16, sw128
    for (int idx = t; idx < 128 * 64; idx += 256) {
        int n = idx >> 6, k = idx & 63;
        float s2 = bn2g[n] * rsqrtf(bn2v[n] + EPSB);
        float w = W1[k * 128 + n] * s2;
        uint32_t off = sw128((uint32_t)(n * 128 + k * 2));
        *(__half*)(g_Wh1 + off) = __float2half_rn(w);
    }
    for (int n = t; n < 128; n += 256) {
        float s2 = bn2g[n] * rsqrtf(bn2v[n] + EPSB);
        g_b1f[n] = s2 * (b1[n] - bn2m[n]) + bn2b[n];
    }

    // L2: slice (g*2+kc) of 16KB each
    for (int idx = t; idx < 256 * 128; idx += 256) {
        int n = idx >> 7, k = idx & 127;
        float s3 = bn3g[n] * rsqrtf(bn3v[n] + EPSB);
        float w = W2[k * 256 + n] * s3;
        int g = n >> 7, kc = k >> 6, nl = n & 127, kl = k & 63;
        uint32_t base = (uint32_t)(g * 2 + kc) * 16384u;
        uint32_t off  = sw128((uint32_t)(nl * 128 + kl * 2));
        *(__half*)(g_Wh2 + base + off) = __float2half_rn(w);
    }
    for (int n = t; n < 256; n += 256) {
        float s3 = bn3g[n] * rsqrtf(bn3v[n] + EPSB);
        g_b2f[n] = s3 * (b2[n] - bn3m[n]) + bn3b[n];
    }

    // L3: slice (kc) of 8KB each: [64n][64k]
    for (int idx = t; idx < 64 * 256; idx += 256) {
        int n = idx / 256, k = idx % 256;
        float w = W3[k * 64 + n];
        int kc = k >> 6, kl = k & 63;
        uint32_t base = (uint32_t)kc * 8192u;
        uint32_t off  = sw128((uint32_t)(n * 128 + kl * 2));
        *(__half*)(g_Wh3 + base + off) = __float2half_rn(w);
    }
}

// ---------------- output init / decode -------------------------------------
__global__ void init_kernel(uint4* __restrict__ o, int n4) {
    int i = blockIdx.x * 256 + threadIdx.x;
    if (i < n4) o[i] = make_uint4(0u, 0u, 0u, 0u);
}
__global__ void decode_kernel(uint4* __restrict__ o, int n4) {
    int i = blockIdx.x * 256 + threadIdx.x;
    if (i < n4) {
        uint4 v = o[i];
        v.x = decf(v.x); v.y = decf(v.y); v.z = decf(v.z); v.w = decf(v.w);
        o[i] = v;
    }
}

// ---------------- SMEM layout ------------------------------------------------
// 6 act slots (32KB each: hi 16KB + lo 16KB), 2 weight buffers (16KB), misc
__host__ __device__ constexpr uint32_t SLOT(int i) { return (uint32_t)i * 32768u; }
static constexpr uint32_t WBUF  = 196608;                // WB0 @ +0, WB1 @ +16384
static constexpr uint32_t MISC  = 229376;
static constexpr uint32_t BIAS1 = MISC;                  // 128 f32
static constexpr uint32_t BIAS2 = MISC + 512;            // 256 f32
static constexpr uint32_t BIAS3 = MISC + 1536;           // 64 f32
static constexpr uint32_t SEGO  = MISC + 1792;           // 128 int
static constexpr uint32_t SMEM_TOTAL = 231680;

// ---------------- warp GEMM over one 64-K chunk (2-pass fp16) ----------------
template<int NT>
__device__ __forceinline__ void mma_kchunk2(
    float (&acc)[2][NT][4],
    uint32_t aHi, uint32_t aLo,   // act chunk base + wm*32*128
    uint32_t bW,                  // weight slice base + n0*128
    int lane)
{
    const int rA  = (lane & 7) + ((lane >> 3) & 1) * 8;
    const int kA8 = ((lane >> 4) & 1) * 8;
    const uint32_t xorA = (uint32_t)((rA & 7) << 4);
    const int rB  = (lane & 7) + ((lane >> 4) & 1) * 8;
    const int kB8 = ((lane >> 3) & 1) * 8;
    const uint32_t xorB = (uint32_t)((lane & 7) << 4);

    #pragma unroll
    for (int ks = 0; ks < 4; ks++) {
        const int k0 = ks * 16;
        uint32_t ah[2][4], al[2][4];
        #pragma unroll
        for (int mt = 0; mt < 2; mt++) {
            uint32_t off = (uint32_t)((mt * 16 + rA) * 128)
                         + (((uint32_t)(k0 + kA8) << 1) ^ xorA);
            ldsm_x4(ah[mt][0], ah[mt][1], ah[mt][2], ah[mt][3], aHi + off);
            ldsm_x4(al[mt][0], al[mt][1], al[mt][2], al[mt][3], aLo + off);
        }
        uint32_t bw[NT][2];
        #pragma unroll
        for (int q = 0; q < NT / 2; q++) {
            uint32_t off = (uint32_t)((q * 16 + rB) * 128)
                         + (((uint32_t)(k0 + kB8) << 1) ^ xorB);
            ldsm_x4(bw[2*q][0], bw[2*q][1], bw[2*q+1][0], bw[2*q+1][1], bW + off);
        }
        #pragma unroll
        for (int mt = 0; mt < 2; mt++)
            #pragma unroll
            for (int nt = 0; nt < NT; nt++) {
                mma_f16(acc[mt][nt], ah[mt], bw[nt]);
                mma_f16(acc[mt][nt], al[mt], bw[nt]);
            }
    }
}

// hidden-layer epilogue: acc -> bias -> relu -> fp16 hi/lo -> act slot (64 cols)
template<int NT>
__device__ __forceinline__ void epi_hidden(
    float (&acc)[2][NT][4], unsigned char* smem, uint32_t outOff,
    const float* sBias, int colBase, int wm, int lane)
{
    const int r0 = lane >> 2;
    #pragma unroll
    for (int mt = 0; mt < 2; mt++) {
        int row1 = wm * 32 + mt * 16 + r0;
        int row2 = row1 + 8;
        #pragma unroll
        for (int nt = 0; nt < NT; nt++) {
            int kl = nt * 8 + (lane & 3) * 2;
            float bi0 = sBias[colBase + kl], bi1 = sBias[colBase + kl + 1];
            {
                float v0 = fmaxf(acc[mt][nt][0] + bi0, 0.f);
                float v1 = fmaxf(acc[mt][nt][1] + bi1, 0.f);
                uint32_t h = pack2h(v0, v1);
                uint32_t l = pack2h(v0 - h_lo(h), v1 - h_hi(h));
                uint32_t off = (uint32_t)(row1 * 128)
                             + (((uint32_t)kl << 1) ^ ((uint32_t)(row1 & 7) << 4));
                *(uint32_t*)(smem + outOff + off)         = h;
                *(uint32_t*)(smem + outOff + 16384 + off) = l;
            }
            {
                float v0 = fmaxf(acc[mt][nt][2] + bi0, 0.f);
                float v1 = fmaxf(acc[mt][nt][3] + bi1, 0.f);
                uint32_t h = pack2h(v0, v1);
                uint32_t l = pack2h(v0 - h_lo(h), v1 - h_hi(h));
                uint32_t off = (uint32_t)(row2 * 128)
                             + (((uint32_t)kl << 1) ^ ((uint32_t)(row2 & 7) << 4));
                *(uint32_t*)(smem + outOff + off)         = h;
                *(uint32_t*)(smem + outOff + 16384 + off) = l;
            }
        }
    }
}

// ---------------- fused MLP + scatter ----------------------------------------
__global__ void __launch_bounds__(256, 1) mlp_kernel(
    const float* __restrict__ pt_fea, const int* __restrict__ pt_ind,
    const float* __restrict__ b3, unsigned* __restrict__ out)
{
    extern __shared__ __align__(1024) unsigned char smem[];
    float* sB1 = (float*)(smem + BIAS1);
    float* sB2 = (float*)(smem + BIAS2);
    float* sB3 = (float*)(smem + BIAS3);
    int*   sSeg = (int*)(smem + SEGO);
    const uint32_t sb = smem_u32(smem);
    const uint32_t WB0 = sb + WBUF, WB1 = sb + WBUF + 16384;

    const int tid = threadIdx.x, wid = tid >> 5, lane = tid & 31;
    const int wm = wid & 3, wn = wid >> 2;
    const int blk = blockIdx.x;
    const uint32_t aWm = (uint32_t)(wm * 32 * 128);

    // ---- prologue: kick S0, stage biases/segs, L0 compute ----
    stage_async(WB0, g_Wh1, 16384, tid); CP_COMMIT();

    if (tid < 128) {
        int gp = blk * 128 + tid;
        if (gp < P_) {
            int ix = pt_ind[3 * gp], iy = pt_ind[3 * gp + 1], iz = pt_ind[3 * gp + 2];
            int bb = (gp >= N_) ? 1 : 0;
            sSeg[tid] = ((bb * G_ + iz) * G_ + iy) * G_ + ix;
        } else sSeg[tid] = -1;
    }
    if (tid < 128) sB1[tid] = g_b1f[tid];
    sB2[tid] = g_b2f[tid];
    if (tid < 64) sB3[tid] = b3[tid];

    // L0: 3 -> 64 scalar fp32, fp16 hi/lo split into slot 0
    {
        int p = tid >> 1, j0 = (tid & 1) * 32;
        int gp = blk * 128 + p;
        float x0 = 0.f, x1 = 0.f, x2 = 0.f;
        if (gp < P_) { x0 = pt_fea[gp*3]; x1 = pt_fea[gp*3+1]; x2 = pt_fea[gp*3+2]; }
        #pragma unroll
        for (int j = 0; j < 32; j += 2) {
            int k = j0 + j;
            float v0 = g_b0f[k]   + x0*g_W0f[k]   + x1*g_W0f[64+k]   + x2*g_W0f[128+k];
            float v1 = g_b0f[k+1] + x0*g_W0f[k+1] + x1*g_W0f[64+k+1] + x2*g_W0f[128+k+1];
            v0 = fmaxf(v0, 0.f); v1 = fmaxf(v1, 0.f);
            uint32_t h = pack2h(v0, v1);
            uint32_t l = pack2h(v0 - h_lo(h), v1 - h_hi(h));
            uint32_t off = sw128((uint32_t)(p * 128 + k * 2));
            *(uint32_t*)(smem + SLOT(0) + off)         = h;
            *(uint32_t*)(smem + SLOT(0) + 16384 + off) = l;
        }
    }
    CP_WAIT0();
    __syncthreads();

    // ---- p0: L1 (64->128), in slot0, out slots 1,2; prefetch S1 ----
    stage_async(WB1, g_Wh2, 16384, tid); CP_COMMIT();
    {
        float acc[2][8][4];
        #pragma unroll
        for (int a = 0; a < 2; a++)
            #pragma unroll
            for (int b = 0; b < 8; b++)
                #pragma unroll
                for (int c = 0; c < 4; c++) acc[a][b][c] = 0.f;
        uint32_t bOff = (uint32_t)(wn * 64 * 128);
        mma_kchunk2<8>(acc, sb + SLOT(0) + aWm, sb + SLOT(0) + 16384 + aWm,
                       WB0 + bOff, lane);
        epi_hidden<8>(acc, smem, SLOT(1 + wn), sB1, wn * 64, wm, lane);
    }
    CP_WAIT0(); __syncthreads();

    // ---- L2 (128->256): g0 over p1,p2 ; g1 over p3,p4 ----
    const int outSlot[4] = {3, 4, 5, 0};
    {
        float acc[2][8][4];
        uint32_t bOff = (uint32_t)(wn * 64 * 128);

        // p1: g0 kc0 on WB1(S1); prefetch S2 -> WB0
        stage_async(WB0, g_Wh2 + 16384, 16384, tid); CP_COMMIT();
        #pragma unroll
        for (int a = 0; a < 2; a++)
            #pragma unroll
            for (int b = 0; b < 8; b++)
                #pragma unroll
                for (int c = 0; c < 4; c++) acc[a][b][c] = 0.f;
        mma_kchunk2<8>(acc, sb + SLOT(1) + aWm, sb + SLOT(1) + 16384 + aWm,
                       WB1 + bOff, lane);
        CP_WAIT0(); __syncthreads();

        // p2: g0 kc1 on WB0(S2); prefetch S3 -> WB1
        stage_async(WB1, g_Wh2 + 32768, 16384, tid); CP_COMMIT();
        mma_kchunk2<8>(acc, sb + SLOT(2) + aWm, sb + SLOT(2) + 16384 + aWm,
                       WB0 + bOff, lane);
        epi_hidden<8>(acc, smem, SLOT(outSlot[wn]), sB2, wn * 64, wm, lane);
        CP_WAIT0(); __syncthreads();

        // p3: g1 kc0 on WB1(S3); prefetch S4 -> WB0
        stage_async(WB0, g_Wh2 + 49152, 16384, tid); CP_COMMIT();
        #pragma unroll
        for (int a = 0; a < 2; a++)
            #pragma unroll
            for (int b = 0; b < 8; b++)
                #pragma unroll
                for (int c = 0; c < 4; c++) acc[a][b][c] = 0.f;
        mma_kchunk2<8>(acc, sb + SLOT(1) + aWm, sb + SLOT(1) + 16384 + aWm,
                       WB1 + bOff, lane);
        CP_WAIT0(); __syncthreads();

        // p4: g1 kc1 on WB0(S4); prefetch S5 -> WB1 (L3 kc0, 8KB)
        stage_async(WB1, g_Wh3, 8192, tid); CP_COMMIT();
        mma_kchunk2<8>(acc, sb + SLOT(2) + aWm, sb + SLOT(2) + 16384 + aWm,
                       WB0 + bOff, lane);
        epi_hidden<8>(acc, smem, SLOT(outSlot[2 + wn]), sB2, 128 + wn * 64, wm, lane);
        CP_WAIT0(); __syncthreads();
    }

    // ---- L3 (256->64) over p5..p8, then scatter ----
    {
        float acc[2][4][4];
        #pragma unroll
        for (int a = 0; a < 2; a++)
            #pragma unroll
            for (int b = 0; b < 4; b++)
                #pragma unroll
                for (int c = 0; c < 4; c++) acc[a][b][c] = 0.f;
        uint32_t bOff = (uint32_t)(wn * 32 * 128);

        // p5: kc0 on WB1(S5); prefetch S6 -> WB0
        stage_async(WB0, g_Wh3 + 8192, 8192, tid); CP_COMMIT();
        mma_kchunk2<4>(acc, sb + SLOT(3) + aWm, sb + SLOT(3) + 16384 + aWm,
                       WB1 + bOff, lane);
        CP_WAIT0(); __syncthreads();

        // p6: kc1 on WB0(S6); prefetch S7 -> WB1
        stage_async(WB1, g_Wh3 + 16384, 8192, tid); CP_COMMIT();
        mma_kchunk2<4>(acc, sb + SLOT(4) + aWm, sb + SLOT(4) + 16384 + aWm,
                       WB0 + bOff, lane);
        CP_WAIT0(); __syncthreads();

        // p7: kc2 on WB1(S7); prefetch S8 -> WB0
        stage_async(WB0, g_Wh3 + 24576, 8192, tid); CP_COMMIT();
        mma_kchunk2<4>(acc, sb + SLOT(5) + aWm, sb + SLOT(5) + 16384 + aWm,
                       WB1 + bOff, lane);
        CP_WAIT0(); __syncthreads();

        // p8: kc3 on WB0(S8)
        mma_kchunk2<4>(acc, sb + SLOT(0) + aWm, sb + SLOT(0) + 16384 + aWm,
                       WB0 + bOff, lane);

        // scatter-max
        const int r0 = lane >> 2;
        #pragma unroll
        for (int mt = 0; mt < 2; mt++) {
            int row1 = wm * 32 + mt * 16 + r0;
            int row2 = row1 + 8;
            int seg1 = sSeg[row1], seg2 = sSeg[row2];
            #pragma unroll
            for (int nt = 0; nt < 4; nt++) {
                int col = wn * 32 + nt * 8 + (lane & 3) * 2;
                float bi0 = sB3[col], bi1 = sB3[col + 1];
                if (seg1 >= 0) {
                    unsigned base = (unsigned)seg1 * 64u + (unsigned)col;
                    atomicMax(out + base,     encf(acc[mt][nt][0] + bi0));
                    atomicMax(out + base + 1, encf(acc[mt][nt][1] + bi1));
                }
                if (seg2 >= 0) {
                    unsigned base = (unsigned)seg2 * 64u + (unsigned)col;
                    atomicMax(out + base,     encf(acc[mt][nt][2] + bi0));
                    atomicMax(out + base + 1, encf(acc[mt][nt][3] + bi1));
                }
            }
        }
    }
}

// ---------------- launcher ---------------------------------------------------
extern "C" void kernel_launch(void* const* d_in, const int* in_sizes, int n_in,
                              void* d_out, int out_size)
{
    const float* pt_fea = (const float*)d_in[0];
    const int*   pt_ind = (const int*)  d_in[1];
    const float *bn0g = (const float*)d_in[2],  *bn0b = (const float*)d_in[3],
                *bn0m = (const float*)d_in[4],  *bn0v = (const float*)d_in[5];
    const float *bn1g = (const float*)d_in[6],  *bn1b = (const float*)d_in[7],
                *bn1m = (const float*)d_in[8],  *bn1v = (const float*)d_in[9];
    const float *bn2g = (const float*)d_in[10], *bn2b = (const float*)d_in[11],
                *bn2m = (const float*)d_in[12], *bn2v = (const float*)d_in[13];
    const float *bn3g = (const float*)d_in[14], *bn3b = (const float*)d_in[15],
                *bn3m = (const float*)d_in[16], *bn3v = (const float*)d_in[17];
    const float *W0 = (const float*)d_in[18], *b0 = (const float*)d_in[19];
    const float *W1 = (const float*)d_in[20], *b1 = (const float*)d_in[21];
    const float *W2 = (const float*)d_in[22], *b2 = (const float*)d_in[23];
    const float *W3 = (const float*)d_in[24], *b3 = (const float*)d_in[25];

    cudaFuncSetAttribute(mlp_kernel, cudaFuncAttributeMaxDynamicSharedMemorySize,
                         SMEM_TOTAL);

    fold_kernel<<<1, 256>>>(bn0g, bn0b, bn0m, bn0v, bn1g, bn1b, bn1m, bn1v,
                            bn2g, bn2b, bn2m, bn2v, bn3g, bn3b, bn3m, bn3v,
                            W0, b0, W1, b1, W2, b2, W3);

    const int n4 = NS_ * OUT_ / 4;
    init_kernel<<<(n4 + 255) / 256, 256>>>((uint4*)d_out, n4);

    mlp_kernel<<<NT_CTA, 256, SMEM_TOTAL>>>(pt_fea, pt_ind, b3, (unsigned*)d_out);

    decode_kernel<<<(n4 + 255) / 256, 256>>>((uint4*)d_out, n4);
}

// round 5
// speedup vs baseline: 3.3909x; 1.4787x over previous
#include <cuda_runtime.h>
#include <cuda_fp16.h>
#include <cstdint>

#define EPSB 1e-5f

static constexpr int B_   = 2;
static constexpr int N_   = 250000;
static constexpr int P_   = B_ * N_;            // 500000
static constexpr int G_   = 64;
static constexpr int NS_  = B_ * G_ * G_ * G_;  // 524288
static constexpr int OUT_ = 64;
static constexpr int TIL  = 128;
static constexpr int NT_CTA = (P_ + TIL - 1) / TIL;  // 3907
static constexpr int THR  = 512;                 // 16 warps

// ---------------- device scratch (no allocation) ---------------------------
__device__ float g_W0f[3 * 64];
__device__ float g_b0f[64];
__device__ float g_b1f[128];
__device__ float g_b2f[256];
// folded, transposed [n][k], single fp16, SW128 pre-swizzled, sliced
__device__ __align__(16) unsigned char g_Wh1[16384];   // [128n][64k]
__device__ __align__(16) unsigned char g_Wh2[65536];   // 4 x 16KB slices (g*2+kc)
__device__ __align__(16) unsigned char g_Wh3[32768];   // 4 x 8KB slices (kc): [64n][64k]

__host__ __device__ __forceinline__ uint32_t sw128(uint32_t o) {
    return o ^ ((o >> 3) & 0x70u);
}

// ---------------- helpers ----------------------------------------------------
__device__ __forceinline__ uint32_t smem_u32(const void* p) {
    uint32_t a;
    asm("{ .reg .u64 t; cvta.to.shared.u64 t, %1; cvt.u32.u64 %0, t; }"
        : "=r"(a) : "l"(p));
    return a;
}
__device__ __forceinline__ void ldsm_x4(uint32_t& r0, uint32_t& r1,
                                        uint32_t& r2, uint32_t& r3, uint32_t addr) {
    asm volatile("ldmatrix.sync.aligned.m8n8.x4.shared.b16 {%0,%1,%2,%3}, [%4];"
                 : "=r"(r0), "=r"(r1), "=r"(r2), "=r"(r3) : "r"(addr));
}
__device__ __forceinline__ void mma_f16(float (&c)[4], const uint32_t (&a)[4],
                                        const uint32_t (&b)[2]) {
    asm volatile("mma.sync.aligned.m16n8k16.row.col.f32.f16.f16.f32 "
                 "{%0,%1,%2,%3}, {%4,%5,%6,%7}, {%8,%9}, {%0,%1,%2,%3};"
                 : "+f"(c[0]), "+f"(c[1]), "+f"(c[2]), "+f"(c[3])
                 : "r"(a[0]), "r"(a[1]), "r"(a[2]), "r"(a[3]), "r"(b[0]), "r"(b[1]));
}
// pack two f32 -> f16x2 word: v0 -> bits[15:0], v1 -> bits[31:16]
__device__ __forceinline__ uint32_t pack2h(float v0, float v1) {
    uint32_t r;
    asm("cvt.rn.f16x2.f32 %0, %1, %2;" : "=r"(r) : "f"(v1), "f"(v0));
    return r;
}
__device__ __forceinline__ float h_lo(uint32_t w) {
    return __half2float(__ushort_as_half((unsigned short)(w & 0xFFFFu)));
}
__device__ __forceinline__ float h_hi(uint32_t w) {
    return __half2float(__ushort_as_half((unsigned short)(w >> 16)));
}

__device__ __forceinline__ unsigned encf(float f) {
    unsigned u = __float_as_uint(f);
    return (u & 0x80000000u) ? ~u : (u | 0x80000000u);
}
__device__ __forceinline__ unsigned decf(unsigned u) {
    if (u == 0u) return 0u;
    return (u & 0x80000000u) ? (u & 0x7FFFFFFFu) : ~u;
}

// cp.async staging (512 threads)
__device__ __forceinline__ void stage_async(uint32_t sdst, const unsigned char* g,
                                            int bytes, int tid) {
    for (int i = tid * 16; i < bytes; i += THR * 16)
        asm volatile("cp.async.cg.shared.global [%0], [%1], 16;"
                     :: "r"(sdst + (uint32_t)i), "l"(g + i));
}
#define CP_COMMIT() asm volatile("cp.async.commit_group;" ::: "memory")
#define CP_WAIT0()  asm volatile("cp.async.wait_group 0;" ::: "memory")

// ---------------- BN folding + weight transform -----------------------------
__global__ void fold_kernel(
    const float* __restrict__ bn0g, const float* __restrict__ bn0b,
    const float* __restrict__ bn0m, const float* __restrict__ bn0v,
    const float* __restrict__ bn1g, const float* __restrict__ bn1b,
    const float* __restrict__ bn1m, const float* __restrict__ bn1v,
    const float* __restrict__ bn2g, const float* __restrict__ bn2b,
    const float* __restrict__ bn2m, const float* __restrict__ bn2v,
    const float* __restrict__ bn3g, const float* __restrict__ bn3b,
    const float* __restrict__ bn3m, const float* __restrict__ bn3v,
    const float* __restrict__ W0, const float* __restrict__ b0,
    const float* __restrict__ W1, const float* __restrict__ b1,
    const float* __restrict__ W2, const float* __restrict__ b2,
    const float* __restrict__ W3)
{
    const int t = threadIdx.x;

    for (int idx = t; idx < 3 * 64; idx += 256) {
        int i = idx / 64, j = idx % 64;
        float s0 = bn0g[i] * rsqrtf(bn0v[i] + EPSB);
        float s1 = bn1g[j] * rsqrtf(bn1v[j] + EPSB);
        g_W0f[idx] = s0 * W0[idx] * s1;
    }
    for (int j = t; j < 64; j += 256) {
        float s1 = bn1g[j] * rsqrtf(bn1v[j] + EPSB);
        float sum = 0.f;
        for (int i = 0; i < 3; i++) {
            float s0 = bn0g[i] * rsqrtf(bn0v[i] + EPSB);
            float c0 = bn0b[i] - bn0m[i] * s0;
            sum += c0 * W0[i * 64 + j];
        }
        g_b0f[j] = s1 * (sum + b0[j] - bn1m[j]) + bn1b[j];
    }

    // L1: [128n][64k] fp16, sw128
    for (int idx = t; idx < 128 * 64; idx += 256) {
        int n = idx >> 6, k = idx & 63;
        float s2 = bn2g[n] * rsqrtf(bn2v[n] + EPSB);
        float w = W1[k * 128 + n] * s2;
        uint32_t off = sw128((uint32_t)(n * 128 + k * 2));
        *(__half*)(g_Wh1 + off) = __float2half_rn(w);
    }
    for (int n = t; n < 128; n += 256) {
        float s2 = bn2g[n] * rsqrtf(bn2v[n] + EPSB);
        g_b1f[n] = s2 * (b1[n] - bn2m[n]) + bn2b[n];
    }

    // L2: slice (g*2+kc) of 16KB each
    for (int idx = t; idx < 256 * 128; idx += 256) {
        int n = idx >> 7, k = idx & 127;
        float s3 = bn3g[n] * rsqrtf(bn3v[n] + EPSB);
        float w = W2[k * 256 + n] * s3;
        int g = n >> 7, kc = k >> 6, nl = n & 127, kl = k & 63;
        uint32_t base = (uint32_t)(g * 2 + kc) * 16384u;
        uint32_t off  = sw128((uint32_t)(nl * 128 + kl * 2));
        *(__half*)(g_Wh2 + base + off) = __float2half_rn(w);
    }
    for (int n = t; n < 256; n += 256) {
        float s3 = bn3g[n] * rsqrtf(bn3v[n] + EPSB);
        g_b2f[n] = s3 * (b2[n] - bn3m[n]) + bn3b[n];
    }

    // L3: slice (kc) of 8KB each: [64n][64k]
    for (int idx = t; idx < 64 * 256; idx += 256) {
        int n = idx / 256, k = idx % 256;
        float w = W3[k * 64 + n];
        int kc = k >> 6, kl = k & 63;
        uint32_t base = (uint32_t)kc * 8192u;
        uint32_t off  = sw128((uint32_t)(n * 128 + kl * 2));
        *(__half*)(g_Wh3 + base + off) = __float2half_rn(w);
    }
}

// ---------------- output init / decode -------------------------------------
__global__ void init_kernel(uint4* __restrict__ o, int n4) {
    int i = blockIdx.x * 256 + threadIdx.x;
    if (i < n4) o[i] = make_uint4(0u, 0u, 0u, 0u);
}
__global__ void decode_kernel(uint4* __restrict__ o, int n4) {
    int i = blockIdx.x * 256 + threadIdx.x;
    if (i < n4) {
        uint4 v = o[i];
        v.x = decf(v.x); v.y = decf(v.y); v.z = decf(v.z); v.w = decf(v.w);
        o[i] = v;
    }
}

// ---------------- SMEM layout ------------------------------------------------
// 6 act slots (32KB each: hi 16KB + lo 16KB), 2 weight buffers (16KB), misc
__host__ __device__ constexpr uint32_t SLOT(int i) { return (uint32_t)i * 32768u; }
static constexpr uint32_t WBUF  = 196608;                // WB0 @ +0, WB1 @ +16384
static constexpr uint32_t MISC  = 229376;
static constexpr uint32_t BIAS1 = MISC;                  // 128 f32
static constexpr uint32_t BIAS2 = MISC + 512;            // 256 f32
static constexpr uint32_t BIAS3 = MISC + 1536;           // 64 f32
static constexpr uint32_t SEGO  = MISC + 1792;           // 128 int
static constexpr uint32_t SMEM_TOTAL = 231680;

// ---------------- warp GEMM over one 64-K chunk (m16 tile, 2-pass fp16) ------
template<int NT>
__device__ __forceinline__ void mma_kchunk2(
    float (&acc)[NT][4],
    uint32_t aHi, uint32_t aLo,   // act chunk base + wm*16*128
    uint32_t bW,                  // weight slice base + wn*(NT*8)*128
    int lane)
{
    const int rA  = (lane & 7) + ((lane >> 3) & 1) * 8;
    const int kA8 = ((lane >> 4) & 1) * 8;
    const uint32_t xorA = (uint32_t)((rA & 7) << 4);
    const int rB  = (lane & 7) + ((lane >> 4) & 1) * 8;
    const int kB8 = ((lane >> 3) & 1) * 8;
    const uint32_t xorB = (uint32_t)((lane & 7) << 4);

    #pragma unroll
    for (int ks = 0; ks < 4; ks++) {
        const int k0 = ks * 16;
        uint32_t ah[4], al[4];
        {
            uint32_t off = (uint32_t)(rA * 128) + (((uint32_t)(k0 + kA8) << 1) ^ xorA);
            ldsm_x4(ah[0], ah[1], ah[2], ah[3], aHi + off);
            ldsm_x4(al[0], al[1], al[2], al[3], aLo + off);
        }
        uint32_t bw[NT][2];
        #pragma unroll
        for (int q = 0; q < NT / 2; q++) {
            uint32_t off = (uint32_t)((q * 16 + rB) * 128)
                         + (((uint32_t)(k0 + kB8) << 1) ^ xorB);
            ldsm_x4(bw[2*q][0], bw[2*q][1], bw[2*q+1][0], bw[2*q+1][1], bW + off);
        }
        #pragma unroll
        for (int nt = 0; nt < NT; nt++) {
            mma_f16(acc[nt], ah, bw[nt]);
            mma_f16(acc[nt], al, bw[nt]);
        }
    }
}

// hidden-layer epilogue: acc -> bias -> relu -> fp16 hi/lo -> act slot (64 cols)
template<int NT>
__device__ __forceinline__ void epi_hidden(
    float (&acc)[NT][4], unsigned char* smem, uint32_t outOff,
    const float* sBias, int colBase, int wm, int lane)
{
    const int r0 = lane >> 2;
    int row1 = wm * 16 + r0;
    int row2 = row1 + 8;
    #pragma unroll
    for (int nt = 0; nt < NT; nt++) {
        int kl = nt * 8 + (lane & 3) * 2;
        float bi0 = sBias[colBase + kl], bi1 = sBias[colBase + kl + 1];
        {
            float v0 = fmaxf(acc[nt][0] + bi0, 0.f);
            float v1 = fmaxf(acc[nt][1] + bi1, 0.f);
            uint32_t h = pack2h(v0, v1);
            uint32_t l = pack2h(v0 - h_lo(h), v1 - h_hi(h));
            uint32_t off = (uint32_t)(row1 * 128)
                         + (((uint32_t)kl << 1) ^ ((uint32_t)(row1 & 7) << 4));
            *(uint32_t*)(smem + outOff + off)         = h;
            *(uint32_t*)(smem + outOff + 16384 + off) = l;
        }
        {
            float v0 = fmaxf(acc[nt][2] + bi0, 0.f);
            float v1 = fmaxf(acc[nt][3] + bi1, 0.f);
            uint32_t h = pack2h(v0, v1);
            uint32_t l = pack2h(v0 - h_lo(h), v1 - h_hi(h));
            uint32_t off = (uint32_t)(row2 * 128)
                         + (((uint32_t)kl << 1) ^ ((uint32_t)(row2 & 7) << 4));
            *(uint32_t*)(smem + outOff + off)         = h;
            *(uint32_t*)(smem + outOff + 16384 + off) = l;
        }
    }
}

// ---------------- fused MLP + scatter ----------------------------------------
__global__ void __launch_bounds__(THR, 1) mlp_kernel(
    const float* __restrict__ pt_fea, const int* __restrict__ pt_ind,
    const float* __restrict__ b3, unsigned* __restrict__ out)
{
    extern __shared__ __align__(1024) unsigned char smem[];
    float* sB1 = (float*)(smem + BIAS1);
    float* sB2 = (float*)(smem + BIAS2);
    float* sB3 = (float*)(smem + BIAS3);
    int*   sSeg = (int*)(smem + SEGO);
    const uint32_t sb = smem_u32(smem);
    const uint32_t WB0 = sb + WBUF, WB1 = sb + WBUF + 16384;

    const int tid = threadIdx.x, wid = tid >> 5, lane = tid & 31;
    const int wm = wid & 7, wn = wid >> 3;   // 8 m-groups x 2 n-groups
    const int blk = blockIdx.x;
    const uint32_t aWm = (uint32_t)(wm * 16 * 128);

    // ---- prologue: kick S0, stage biases/segs, L0 compute ----
    stage_async(WB0, g_Wh1, 16384, tid); CP_COMMIT();

    if (tid < 128) {
        int gp = blk * 128 + tid;
        if (gp < P_) {
            int ix = pt_ind[3 * gp], iy = pt_ind[3 * gp + 1], iz = pt_ind[3 * gp + 2];
            int bb = (gp >= N_) ? 1 : 0;
            sSeg[tid] = ((bb * G_ + iz) * G_ + iy) * G_ + ix;
        } else sSeg[tid] = -1;
    }
    if (tid < 128) sB1[tid] = g_b1f[tid];
    if (tid < 256) sB2[tid] = g_b2f[tid];
    if (tid < 64)  sB3[tid] = b3[tid];

    // L0: 3 -> 64 scalar fp32, fp16 hi/lo split into slot 0
    {
        int p = tid >> 2, j0 = (tid & 3) * 16;
        int gp = blk * 128 + p;
        float x0 = 0.f, x1 = 0.f, x2 = 0.f;
        if (gp < P_) { x0 = pt_fea[gp*3]; x1 = pt_fea[gp*3+1]; x2 = pt_fea[gp*3+2]; }
        #pragma unroll
        for (int j = 0; j < 16; j += 2) {
            int k = j0 + j;
            float v0 = g_b0f[k]   + x0*g_W0f[k]   + x1*g_W0f[64+k]   + x2*g_W0f[128+k];
            float v1 = g_b0f[k+1] + x0*g_W0f[k+1] + x1*g_W0f[64+k+1] + x2*g_W0f[128+k+1];
            v0 = fmaxf(v0, 0.f); v1 = fmaxf(v1, 0.f);
            uint32_t h = pack2h(v0, v1);
            uint32_t l = pack2h(v0 - h_lo(h), v1 - h_hi(h));
            uint32_t off = sw128((uint32_t)(p * 128 + k * 2));
            *(uint32_t*)(smem + SLOT(0) + off)         = h;
            *(uint32_t*)(smem + SLOT(0) + 16384 + off) = l;
        }
    }
    CP_WAIT0();
    __syncthreads();

    // ---- p0: L1 (64->128), in slot0, out slots 1,2; prefetch S1 ----
    stage_async(WB1, g_Wh2, 16384, tid); CP_COMMIT();
    {
        float acc[8][4];
        #pragma unroll
        for (int b = 0; b < 8; b++)
            #pragma unroll
            for (int c = 0; c < 4; c++) acc[b][c] = 0.f;
        uint32_t bOff = (uint32_t)(wn * 64 * 128);
        mma_kchunk2<8>(acc, sb + SLOT(0) + aWm, sb + SLOT(0) + 16384 + aWm,
                       WB0 + bOff, lane);
        epi_hidden<8>(acc, smem, SLOT(1 + wn), sB1, wn * 64, wm, lane);
    }
    CP_WAIT0(); __syncthreads();

    // ---- L2 (128->256): g0 over p1,p2 ; g1 over p3,p4 ----
    const int outSlot[4] = {3, 4, 5, 0};
    {
        float acc[8][4];
        uint32_t bOff = (uint32_t)(wn * 64 * 128);

        // p1: g0 kc0 on WB1(S1); prefetch S2 -> WB0
        stage_async(WB0, g_Wh2 + 16384, 16384, tid); CP_COMMIT();
        #pragma unroll
        for (int b = 0; b < 8; b++)
            #pragma unroll
            for (int c = 0; c < 4; c++) acc[b][c] = 0.f;
        mma_kchunk2<8>(acc, sb + SLOT(1) + aWm, sb + SLOT(1) + 16384 + aWm,
                       WB1 + bOff, lane);
        CP_WAIT0(); __syncthreads();

        // p2: g0 kc1 on WB0(S2); prefetch S3 -> WB1
        stage_async(WB1, g_Wh2 + 32768, 16384, tid); CP_COMMIT();
        mma_kchunk2<8>(acc, sb + SLOT(2) + aWm, sb + SLOT(2) + 16384 + aWm,
                       WB0 + bOff, lane);
        epi_hidden<8>(acc, smem, SLOT(outSlot[wn]), sB2, wn * 64, wm, lane);
        CP_WAIT0(); __syncthreads();

        // p3: g1 kc0 on WB1(S3); prefetch S4 -> WB0
        stage_async(WB0, g_Wh2 + 49152, 16384, tid); CP_COMMIT();
        #pragma unroll
        for (int b = 0; b < 8; b++)
            #pragma unroll
            for (int c = 0; c < 4; c++) acc[b][c] = 0.f;
        mma_kchunk2<8>(acc, sb + SLOT(1) + aWm, sb + SLOT(1) + 16384 + aWm,
                       WB1 + bOff, lane);
        CP_WAIT0(); __syncthreads();

        // p4: g1 kc1 on WB0(S4); prefetch S5 -> WB1 (L3 kc0, 8KB)
        stage_async(WB1, g_Wh3, 8192, tid); CP_COMMIT();
        mma_kchunk2<8>(acc, sb + SLOT(2) + aWm, sb + SLOT(2) + 16384 + aWm,
                       WB0 + bOff, lane);
        epi_hidden<8>(acc, smem, SLOT(outSlot[2 + wn]), sB2, 128 + wn * 64, wm, lane);
        CP_WAIT0(); __syncthreads();
    }

    // ---- L3 (256->64) over p5..p8, then scatter ----
    {
        float acc[4][4];
        #pragma unroll
        for (int b = 0; b < 4; b++)
            #pragma unroll
            for (int c = 0; c < 4; c++) acc[b][c] = 0.f;
        uint32_t bOff = (uint32_t)(wn * 32 * 128);

        // p5: kc0 on WB1(S5); prefetch S6 -> WB0
        stage_async(WB0, g_Wh3 + 8192, 8192, tid); CP_COMMIT();
        mma_kchunk2<4>(acc, sb + SLOT(3) + aWm, sb + SLOT(3) + 16384 + aWm,
                       WB1 + bOff, lane);
        CP_WAIT0(); __syncthreads();

        // p6: kc1 on WB0(S6); prefetch S7 -> WB1
        stage_async(WB1, g_Wh3 + 16384, 8192, tid); CP_COMMIT();
        mma_kchunk2<4>(acc, sb + SLOT(4) + aWm, sb + SLOT(4) + 16384 + aWm,
                       WB0 + bOff, lane);
        CP_WAIT0(); __syncthreads();

        // p7: kc2 on WB1(S7); prefetch S8 -> WB0
        stage_async(WB0, g_Wh3 + 24576, 8192, tid); CP_COMMIT();
        mma_kchunk2<4>(acc, sb + SLOT(5) + aWm, sb + SLOT(5) + 16384 + aWm,
                       WB1 + bOff, lane);
        CP_WAIT0(); __syncthreads();

        // p8: kc3 on WB0(S8)
        mma_kchunk2<4>(acc, sb + SLOT(0) + aWm, sb + SLOT(0) + 16384 + aWm,
                       WB0 + bOff, lane);

        // scatter-max
        const int r0 = lane >> 2;
        int row1 = wm * 16 + r0;
        int row2 = row1 + 8;
        int seg1 = sSeg[row1], seg2 = sSeg[row2];
        #pragma unroll
        for (int nt = 0; nt < 4; nt++) {
            int col = wn * 32 + nt * 8 + (lane & 3) * 2;
            float bi0 = sB3[col], bi1 = sB3[col + 1];
            if (seg1 >= 0) {
                unsigned base = (unsigned)seg1 * 64u + (unsigned)col;
                atomicMax(out + base,     encf(acc[nt][0] + bi0));
                atomicMax(out + base + 1, encf(acc[nt][1] + bi1));
            }
            if (seg2 >= 0) {
                unsigned base = (unsigned)seg2 * 64u + (unsigned)col;
                atomicMax(out + base,     encf(acc[nt][2] + bi0));
                atomicMax(out + base + 1, encf(acc[nt][3] + bi1));
            }
        }
    }
}

// ---------------- launcher ---------------------------------------------------
extern "C" void kernel_launch(void* const* d_in, const int* in_sizes, int n_in,
                              void* d_out, int out_size)
{
    const float* pt_fea = (const float*)d_in[0];
    const int*   pt_ind = (const int*)  d_in[1];
    const float *bn0g = (const float*)d_in[2],  *bn0b = (const float*)d_in[3],
                *bn0m = (const float*)d_in[4],  *bn0v = (const float*)d_in[5];
    const float *bn1g = (const float*)d_in[6],  *bn1b = (const float*)d_in[7],
                *bn1m = (const float*)d_in[8],  *bn1v = (const float*)d_in[9];
    const float *bn2g = (const float*)d_in[10], *bn2b = (const float*)d_in[11],
                *bn2m = (const float*)d_in[12], *bn2v = (const float*)d_in[13];
    const float *bn3g = (const float*)d_in[14], *bn3b = (const float*)d_in[15],
                *bn3m = (const float*)d_in[16], *bn3v = (const float*)d_in[17];
    const float *W0 = (const float*)d_in[18], *b0 = (const float*)d_in[19];
    const float *W1 = (const float*)d_in[20], *b1 = (const float*)d_in[21];
    const float *W2 = (const float*)d_in[22], *b2 = (const float*)d_in[23];
    const float *W3 = (const float*)d_in[24], *b3 = (const float*)d_in[25];

    cudaFuncSetAttribute(mlp_kernel, cudaFuncAttributeMaxDynamicSharedMemorySize,
                         SMEM_TOTAL);

    fold_kernel<<<1, 256>>>(bn0g, bn0b, bn0m, bn0v, bn1g, bn1b, bn1m, bn1v,
                            bn2g, bn2b, bn2m, bn2v, bn3g, bn3b, bn3m, bn3v,
                            W0, b0, W1, b1, W2, b2, W3);

    const int n4 = NS_ * OUT_ / 4;
    init_kernel<<<(n4 + 255) / 256, 256>>>((uint4*)d_out, n4);

    mlp_kernel<<<NT_CTA, THR, SMEM_TOTAL>>>(pt_fea, pt_ind, b3, (unsigned*)d_out);

    decode_kernel<<<(n4 + 255) / 256, 256>>>((uint4*)d_out, n4);
}

// round 6
// speedup vs baseline: 4.3335x; 1.2780x over previous
#include <cuda_runtime.h>
#include <cuda_fp16.h>
#include <cstdint>

#define EPSB 1e-5f

static constexpr int B_   = 2;
static constexpr int N_   = 250000;
static constexpr int P_   = B_ * N_;            // 500000
static constexpr int G_   = 64;
static constexpr int NS_  = B_ * G_ * G_ * G_;  // 524288
static constexpr int OUT_ = 64;
static constexpr int TIL  = 128;
static constexpr int NT_CTA = (P_ + TIL - 1) / TIL;  // 3907
static constexpr int THR  = 512;                 // 16 warps

// ---------------- device scratch (no allocation) ---------------------------
__device__ float g_W0f[3 * 64];
__device__ float g_b0f[64];
__device__ float g_b1f[128];
__device__ float g_b2f[256];
// folded, transposed [n][k], single fp16, SW128 pre-swizzled, sliced
__device__ __align__(16) unsigned char g_Wh1[16384];   // [128n][64k]
__device__ __align__(16) unsigned char g_Wh2[65536];   // 4 x 16KB slices (g*2+kc)
__device__ __align__(16) unsigned char g_Wh3[32768];   // 4 x 8KB slices (kc): [64n][64k]

__host__ __device__ __forceinline__ uint32_t sw128(uint32_t o) {
    return o ^ ((o >> 3) & 0x70u);
}

// ---------------- helpers ----------------------------------------------------
__device__ __forceinline__ uint32_t smem_u32(const void* p) {
    uint32_t a;
    asm("{ .reg .u64 t; cvta.to.shared.u64 t, %1; cvt.u32.u64 %0, t; }"
        : "=r"(a) : "l"(p));
    return a;
}
__device__ __forceinline__ void ldsm_x4(uint32_t& r0, uint32_t& r1,
                                        uint32_t& r2, uint32_t& r3, uint32_t addr) {
    asm volatile("ldmatrix.sync.aligned.m8n8.x4.shared.b16 {%0,%1,%2,%3}, [%4];"
                 : "=r"(r0), "=r"(r1), "=r"(r2), "=r"(r3) : "r"(addr));
}
__device__ __forceinline__ void mma_f16(float (&c)[4], const uint32_t (&a)[4],
                                        const uint32_t (&b)[2]) {
    asm volatile("mma.sync.aligned.m16n8k16.row.col.f32.f16.f16.f32 "
                 "{%0,%1,%2,%3}, {%4,%5,%6,%7}, {%8,%9}, {%0,%1,%2,%3};"
                 : "+f"(c[0]), "+f"(c[1]), "+f"(c[2]), "+f"(c[3])
                 : "r"(a[0]), "r"(a[1]), "r"(a[2]), "r"(a[3]), "r"(b[0]), "r"(b[1]));
}
// pack two f32 -> f16x2 word: v0 -> bits[15:0], v1 -> bits[31:16]
__device__ __forceinline__ uint32_t pack2h(float v0, float v1) {
    uint32_t r;
    asm("cvt.rn.f16x2.f32 %0, %1, %2;" : "=r"(r) : "f"(v1), "f"(v0));
    return r;
}

__device__ __forceinline__ unsigned encf(float f) {
    unsigned u = __float_as_uint(f);
    return (u & 0x80000000u) ? ~u : (u | 0x80000000u);
}
__device__ __forceinline__ unsigned decf(unsigned u) {
    if (u == 0u) return 0u;
    return (u & 0x80000000u) ? (u & 0x7FFFFFFFu) : ~u;
}

// cp.async staging (512 threads)
__device__ __forceinline__ void stage_async(uint32_t sdst, const unsigned char* g,
                                            int bytes, int tid) {
    for (int i = tid * 16; i < bytes; i += THR * 16)
        asm volatile("cp.async.cg.shared.global [%0], [%1], 16;"
                     :: "r"(sdst + (uint32_t)i), "l"(g + i));
}
#define CP_COMMIT() asm volatile("cp.async.commit_group;" ::: "memory")
#define CP_WAIT0()  asm volatile("cp.async.wait_group 0;" ::: "memory")

// ---------------- BN folding + weight transform -----------------------------
__global__ void fold_kernel(
    const float* __restrict__ bn0g, const float* __restrict__ bn0b,
    const float* __restrict__ bn0m, const float* __restrict__ bn0v,
    const float* __restrict__ bn1g, const float* __restrict__ bn1b,
    const float* __restrict__ bn1m, const float* __restrict__ bn1v,
    const float* __restrict__ bn2g, const float* __restrict__ bn2b,
    const float* __restrict__ bn2m, const float* __restrict__ bn2v,
    const float* __restrict__ bn3g, const float* __restrict__ bn3b,
    const float* __restrict__ bn3m, const float* __restrict__ bn3v,
    const float* __restrict__ W0, const float* __restrict__ b0,
    const float* __restrict__ W1, const float* __restrict__ b1,
    const float* __restrict__ W2, const float* __restrict__ b2,
    const float* __restrict__ W3)
{
    const int t = threadIdx.x;

    for (int idx = t; idx < 3 * 64; idx += 256) {
        int i = idx / 64, j = idx % 64;
        float s0 = bn0g[i] * rsqrtf(bn0v[i] + EPSB);
        float s1 = bn1g[j] * rsqrtf(bn1v[j] + EPSB);
        g_W0f[idx] = s0 * W0[idx] * s1;
    }
    for (int j = t; j < 64; j += 256) {
        float s1 = bn1g[j] * rsqrtf(bn1v[j] + EPSB);
        float sum = 0.f;
        for (int i = 0; i < 3; i++) {
            float s0 = bn0g[i] * rsqrtf(bn0v[i] + EPSB);
            float c0 = bn0b[i] - bn0m[i] * s0;
            sum += c0 * W0[i * 64 + j];
        }
        g_b0f[j] = s1 * (sum + b0[j] - bn1m[j]) + bn1b[j];
    }

    // L1: [128n][64k] fp16, sw128
    for (int idx = t; idx < 128 * 64; idx += 256) {
        int n = idx >> 6, k = idx & 63;
        float s2 = bn2g[n] * rsqrtf(bn2v[n] + EPSB);
        float w = W1[k * 128 + n] * s2;
        uint32_t off = sw128((uint32_t)(n * 128 + k * 2));
        *(__half*)(g_Wh1 + off) = __float2half_rn(w);
    }
    for (int n = t; n < 128; n += 256) {
        float s2 = bn2g[n] * rsqrtf(bn2v[n] + EPSB);
        g_b1f[n] = s2 * (b1[n] - bn2m[n]) + bn2b[n];
    }

    // L2: slice (g*2+kc) of 16KB each
    for (int idx = t; idx < 256 * 128; idx += 256) {
        int n = idx >> 7, k = idx & 127;
        float s3 = bn3g[n] * rsqrtf(bn3v[n] + EPSB);
        float w = W2[k * 256 + n] * s3;
        int g = n >> 7, kc = k >> 6, nl = n & 127, kl = k & 63;
        uint32_t base = (uint32_t)(g * 2 + kc) * 16384u;
        uint32_t off  = sw128((uint32_t)(nl * 128 + kl * 2));
        *(__half*)(g_Wh2 + base + off) = __float2half_rn(w);
    }
    for (int n = t; n < 256; n += 256) {
        float s3 = bn3g[n] * rsqrtf(bn3v[n] + EPSB);
        g_b2f[n] = s3 * (b2[n] - bn3m[n]) + bn3b[n];
    }

    // L3: slice (kc) of 8KB each: [64n][64k]
    for (int idx = t; idx < 64 * 256; idx += 256) {
        int n = idx / 256, k = idx % 256;
        float w = W3[k * 64 + n];
        int kc = k >> 6, kl = k & 63;
        uint32_t base = (uint32_t)kc * 8192u;
        uint32_t off  = sw128((uint32_t)(n * 128 + kl * 2));
        *(__half*)(g_Wh3 + base + off) = __float2half_rn(w);
    }
}

// ---------------- output init / decode -------------------------------------
__global__ void init_kernel(uint4* __restrict__ o, int n4) {
    int i = blockIdx.x * 256 + threadIdx.x;
    if (i < n4) o[i] = make_uint4(0u, 0u, 0u, 0u);
}
__global__ void decode_kernel(uint4* __restrict__ o, int n4) {
    int i = blockIdx.x * 256 + threadIdx.x;
    if (i < n4) {
        uint4 v = o[i];
        v.x = decf(v.x); v.y = decf(v.y); v.z = decf(v.z); v.w = decf(v.w);
        o[i] = v;
    }
}

// ---------------- SMEM layout ------------------------------------------------
// 6 act slots (16KB each, single fp16), 2 weight buffers (16KB), misc
__host__ __device__ constexpr uint32_t SLOT(int i) { return (uint32_t)i * 16384u; }
static constexpr uint32_t WBUF  = 98304;                 // WB0 @ +0, WB1 @ +16384
static constexpr uint32_t MISC  = 131072;
static constexpr uint32_t BIAS1 = MISC;                  // 128 f32
static constexpr uint32_t BIAS2 = MISC + 512;            // 256 f32
static constexpr uint32_t BIAS3 = MISC + 1536;           // 64 f32
static constexpr uint32_t SEGO  = MISC + 1792;           // 128 int
static constexpr uint32_t SMEM_TOTAL = 133376;

// ---------------- warp GEMM over one 64-K chunk (m16 tile, 1-pass fp16) ------
template<int NT>
__device__ __forceinline__ void mma_kchunk1(
    float (&acc)[NT][4],
    uint32_t aW,                  // act chunk base + wm*16*128
    uint32_t bW,                  // weight slice base + wn*(NT*8)*128
    int lane)
{
    const int rA  = (lane & 7) + ((lane >> 3) & 1) * 8;
    const int kA8 = ((lane >> 4) & 1) * 8;
    const uint32_t xorA = (uint32_t)((rA & 7) << 4);
    const int rB  = (lane & 7) + ((lane >> 4) & 1) * 8;
    const int kB8 = ((lane >> 3) & 1) * 8;
    const uint32_t xorB = (uint32_t)((lane & 7) << 4);

    #pragma unroll
    for (int ks = 0; ks < 4; ks++) {
        const int k0 = ks * 16;
        uint32_t ah[4];
        {
            uint32_t off = (uint32_t)(rA * 128) + (((uint32_t)(k0 + kA8) << 1) ^ xorA);
            ldsm_x4(ah[0], ah[1], ah[2], ah[3], aW + off);
        }
        uint32_t bw[NT][2];
        #pragma unroll
        for (int q = 0; q < NT / 2; q++) {
            uint32_t off = (uint32_t)((q * 16 + rB) * 128)
                         + (((uint32_t)(k0 + kB8) << 1) ^ xorB);
            ldsm_x4(bw[2*q][0], bw[2*q][1], bw[2*q+1][0], bw[2*q+1][1], bW + off);
        }
        #pragma unroll
        for (int nt = 0; nt < NT; nt++)
            mma_f16(acc[nt], ah, bw[nt]);
    }
}

// hidden-layer epilogue: acc -> bias -> relu -> fp16 -> act slot (64 cols)
template<int NT>
__device__ __forceinline__ void epi_hidden(
    float (&acc)[NT][4], unsigned char* smem, uint32_t outOff,
    const float* sBias, int colBase, int wm, int lane)
{
    const int r0 = lane >> 2;
    int row1 = wm * 16 + r0;
    int row2 = row1 + 8;
    #pragma unroll
    for (int nt = 0; nt < NT; nt++) {
        int kl = nt * 8 + (lane & 3) * 2;
        float bi0 = sBias[colBase + kl], bi1 = sBias[colBase + kl + 1];
        {
            float v0 = fmaxf(acc[nt][0] + bi0, 0.f);
            float v1 = fmaxf(acc[nt][1] + bi1, 0.f);
            uint32_t off = (uint32_t)(row1 * 128)
                         + (((uint32_t)kl << 1) ^ ((uint32_t)(row1 & 7) << 4));
            *(uint32_t*)(smem + outOff + off) = pack2h(v0, v1);
        }
        {
            float v0 = fmaxf(acc[nt][2] + bi0, 0.f);
            float v1 = fmaxf(acc[nt][3] + bi1, 0.f);
            uint32_t off = (uint32_t)(row2 * 128)
                         + (((uint32_t)kl << 1) ^ ((uint32_t)(row2 & 7) << 4));
            *(uint32_t*)(smem + outOff + off) = pack2h(v0, v1);
        }
    }
}

// ---------------- fused MLP + scatter ----------------------------------------
__global__ void __launch_bounds__(THR, 1) mlp_kernel(
    const float* __restrict__ pt_fea, const int* __restrict__ pt_ind,
    const float* __restrict__ b3, unsigned* __restrict__ out)
{
    extern __shared__ __align__(1024) unsigned char smem[];
    float* sB1 = (float*)(smem + BIAS1);
    float* sB2 = (float*)(smem + BIAS2);
    float* sB3 = (float*)(smem + BIAS3);
    int*   sSeg = (int*)(smem + SEGO);
    const uint32_t sb = smem_u32(smem);
    const uint32_t WB0 = sb + WBUF, WB1 = sb + WBUF + 16384;

    const int tid = threadIdx.x, wid = tid >> 5, lane = tid & 31;
    const int wm = wid & 7, wn = wid >> 3;   // 8 m-groups x 2 n-groups
    const int blk = blockIdx.x;
    const uint32_t aWm = (uint32_t)(wm * 16 * 128);

    // ---- prologue: kick S0, stage biases/segs, L0 compute ----
    stage_async(WB0, g_Wh1, 16384, tid); CP_COMMIT();

    if (tid < 128) {
        int gp = blk * 128 + tid;
        if (gp < P_) {
            int ix = pt_ind[3 * gp], iy = pt_ind[3 * gp + 1], iz = pt_ind[3 * gp + 2];
            int bb = (gp >= N_) ? 1 : 0;
            sSeg[tid] = ((bb * G_ + iz) * G_ + iy) * G_ + ix;
        } else sSeg[tid] = -1;
    }
    if (tid < 128) sB1[tid] = g_b1f[tid];
    if (tid < 256) sB2[tid] = g_b2f[tid];
    if (tid < 64)  sB3[tid] = b3[tid];

    // L0: 3 -> 64 scalar fp32, fp16 into slot 0
    {
        int p = tid >> 2, j0 = (tid & 3) * 16;
        int gp = blk * 128 + p;
        float x0 = 0.f, x1 = 0.f, x2 = 0.f;
        if (gp < P_) { x0 = pt_fea[gp*3]; x1 = pt_fea[gp*3+1]; x2 = pt_fea[gp*3+2]; }
        #pragma unroll
        for (int j = 0; j < 16; j += 2) {
            int k = j0 + j;
            float v0 = g_b0f[k]   + x0*g_W0f[k]   + x1*g_W0f[64+k]   + x2*g_W0f[128+k];
            float v1 = g_b0f[k+1] + x0*g_W0f[k+1] + x1*g_W0f[64+k+1] + x2*g_W0f[128+k+1];
            v0 = fmaxf(v0, 0.f); v1 = fmaxf(v1, 0.f);
            uint32_t off = sw128((uint32_t)(p * 128 + k * 2));
            *(uint32_t*)(smem + SLOT(0) + off) = pack2h(v0, v1);
        }
    }
    CP_WAIT0();
    __syncthreads();

    // ---- p0: L1 (64->128), in slot0, out slots 1,2; prefetch S1 ----
    stage_async(WB1, g_Wh2, 16384, tid); CP_COMMIT();
    {
        float acc[8][4];
        #pragma unroll
        for (int b = 0; b < 8; b++)
            #pragma unroll
            for (int c = 0; c < 4; c++) acc[b][c] = 0.f;
        uint32_t bOff = (uint32_t)(wn * 64 * 128);
        mma_kchunk1<8>(acc, sb + SLOT(0) + aWm, WB0 + bOff, lane);
        epi_hidden<8>(acc, smem, SLOT(1 + wn), sB1, wn * 64, wm, lane);
    }
    CP_WAIT0(); __syncthreads();

    // ---- L2 (128->256): g0 over p1,p2 ; g1 over p3,p4 ----
    const int outSlot[4] = {3, 4, 5, 0};
    {
        float acc[8][4];
        uint32_t bOff = (uint32_t)(wn * 64 * 128);

        // p1: g0 kc0 on WB1(S1); prefetch S2 -> WB0
        stage_async(WB0, g_Wh2 + 16384, 16384, tid); CP_COMMIT();
        #pragma unroll
        for (int b = 0; b < 8; b++)
            #pragma unroll
            for (int c = 0; c < 4; c++) acc[b][c] = 0.f;
        mma_kchunk1<8>(acc, sb + SLOT(1) + aWm, WB1 + bOff, lane);
        CP_WAIT0(); __syncthreads();

        // p2: g0 kc1 on WB0(S2); prefetch S3 -> WB1
        stage_async(WB1, g_Wh2 + 32768, 16384, tid); CP_COMMIT();
        mma_kchunk1<8>(acc, sb + SLOT(2) + aWm, WB0 + bOff, lane);
        epi_hidden<8>(acc, smem, SLOT(outSlot[wn]), sB2, wn * 64, wm, lane);
        CP_WAIT0(); __syncthreads();

        // p3: g1 kc0 on WB1(S3); prefetch S4 -> WB0
        stage_async(WB0, g_Wh2 + 49152, 16384, tid); CP_COMMIT();
        #pragma unroll
        for (int b = 0; b < 8; b++)
            #pragma unroll
            for (int c = 0; c < 4; c++) acc[b][c] = 0.f;
        mma_kchunk1<8>(acc, sb + SLOT(1) + aWm, WB1 + bOff, lane);
        CP_WAIT0(); __syncthreads();

        // p4: g1 kc1 on WB0(S4); prefetch S5 -> WB1 (L3 kc0, 8KB)
        stage_async(WB1, g_Wh3, 8192, tid); CP_COMMIT();
        mma_kchunk1<8>(acc, sb + SLOT(2) + aWm, WB0 + bOff, lane);
        epi_hidden<8>(acc, smem, SLOT(outSlot[2 + wn]), sB2, 128 + wn * 64, wm, lane);
        CP_WAIT0(); __syncthreads();
    }

    // ---- L3 (256->64) over p5..p8, then scatter ----
    {
        float acc[4][4];
        #pragma unroll
        for (int b = 0; b < 4; b++)
            #pragma unroll
            for (int c = 0; c < 4; c++) acc[b][c] = 0.f;
        uint32_t bOff = (uint32_t)(wn * 32 * 128);

        // p5: kc0 on WB1(S5); prefetch S6 -> WB0
        stage_async(WB0, g_Wh3 + 8192, 8192, tid); CP_COMMIT();
        mma_kchunk1<4>(acc, sb + SLOT(3) + aWm, WB1 + bOff, lane);
        CP_WAIT0(); __syncthreads();

        // p6: kc1 on WB0(S6); prefetch S7 -> WB1
        stage_async(WB1, g_Wh3 + 16384, 8192, tid); CP_COMMIT();
        mma_kchunk1<4>(acc, sb + SLOT(4) + aWm, WB0 + bOff, lane);
        CP_WAIT0(); __syncthreads();

        // p7: kc2 on WB1(S7); prefetch S8 -> WB0
        stage_async(WB0, g_Wh3 + 24576, 8192, tid); CP_COMMIT();
        mma_kchunk1<4>(acc, sb + SLOT(5) + aWm, WB1 + bOff, lane);
        CP_WAIT0(); __syncthreads();

        // p8: kc3 on WB0(S8)
        mma_kchunk1<4>(acc, sb + SLOT(0) + aWm, WB0 + bOff, lane);

        // scatter-max
        const int r0 = lane >> 2;
        int row1 = wm * 16 + r0;
        int row2 = row1 + 8;
        int seg1 = sSeg[row1], seg2 = sSeg[row2];
        #pragma unroll
        for (int nt = 0; nt < 4; nt++) {
            int col = wn * 32 + nt * 8 + (lane & 3) * 2;
            float bi0 = sB3[col], bi1 = sB3[col + 1];
            if (seg1 >= 0) {
                unsigned base = (unsigned)seg1 * 64u + (unsigned)col;
                atomicMax(out + base,     encf(acc[nt][0] + bi0));
                atomicMax(out + base + 1, encf(acc[nt][1] + bi1));
            }
            if (seg2 >= 0) {
                unsigned base = (unsigned)seg2 * 64u + (unsigned)col;
                atomicMax(out + base,     encf(acc[nt][2] + bi0));
                atomicMax(out + base + 1, encf(acc[nt][3] + bi1));
            }
        }
    }
}

// ---------------- launcher ---------------------------------------------------
extern "C" void kernel_launch(void* const* d_in, const int* in_sizes, int n_in,
                              void* d_out, int out_size)
{
    const float* pt_fea = (const float*)d_in[0];
    const int*   pt_ind = (const int*)  d_in[1];
    const float *bn0g = (const float*)d_in[2],  *bn0b = (const float*)d_in[3],
                *bn0m = (const float*)d_in[4],  *bn0v = (const float*)d_in[5];
    const float *bn1g = (const float*)d_in[6],  *bn1b = (const float*)d_in[7],
                *bn1m = (const float*)d_in[8],  *bn1v = (const float*)d_in[9];
    const float *bn2g = (const float*)d_in[10], *bn2b = (const float*)d_in[11],
                *bn2m = (const float*)d_in[12], *bn2v = (const float*)d_in[13];
    const float *bn3g = (const float*)d_in[14], *bn3b = (const float*)d_in[15],
                *bn3m = (const float*)d_in[16], *bn3v = (const float*)d_in[17];
    const float *W0 = (const float*)d_in[18], *b0 = (const float*)d_in[19];
    const float *W1 = (const float*)d_in[20], *b1 = (const float*)d_in[21];
    const float *W2 = (const float*)d_in[22], *b2 = (const float*)d_in[23];
    const float *W3 = (const float*)d_in[24], *b3 = (const float*)d_in[25];

    cudaFuncSetAttribute(mlp_kernel, cudaFuncAttributeMaxDynamicSharedMemorySize,
                         SMEM_TOTAL);

    fold_kernel<<<1, 256>>>(bn0g, bn0b, bn0m, bn0v, bn1g, bn1b, bn1m, bn1v,
                            bn2g, bn2b, bn2m, bn2v, bn3g, bn3b, bn3m, bn3v,
                            W0, b0, W1, b1, W2, b2, W3);

    const int n4 = NS_ * OUT_ / 4;
    init_kernel<<<(n4 + 255) / 256, 256>>>((uint4*)d_out, n4);

    mlp_kernel<<<NT_CTA, THR, SMEM_TOTAL>>>(pt_fea, pt_ind, b3, (unsigned*)d_out);

    decode_kernel<<<(n4 + 255) / 256, 256>>>((uint4*)d_out, n4);
}

// round 7
// speedup vs baseline: 5.6419x; 1.3019x over previous
#include <cuda_runtime.h>
#include <cuda_fp16.h>
#include <cstdint>

#define EPSB 1e-5f

static constexpr int B_   = 2;
static constexpr int N_   = 250000;
static constexpr int P_   = B_ * N_;            // 500000
static constexpr int G_   = 64;
static constexpr int NS_  = B_ * G_ * G_ * G_;  // 524288
static constexpr int OUT_ = 64;
static constexpr int TIL  = 256;                // points per CTA
static constexpr int NT_CTA = (P_ + TIL - 1) / TIL;  // 1954
static constexpr int THR  = 512;                // 16 warps

// ---------------- device scratch (no allocation) ---------------------------
__device__ float g_W0f[3 * 64];
__device__ float g_b0f[64];
__device__ float g_b1f[128];
__device__ float g_b2f[256];
// folded, transposed [n][k], single fp16, SW128 pre-swizzled, sliced
__device__ __align__(16) unsigned char g_Wh1[16384];   // [128n][64k]
__device__ __align__(16) unsigned char g_Wh2[65536];   // 4 x 16KB slices (g*2+kc)
__device__ __align__(16) unsigned char g_Wh3[32768];   // 4 x 8KB slices (kc): [64n][64k]

__host__ __device__ __forceinline__ uint32_t sw128(uint32_t o) {
    return o ^ ((o >> 3) & 0x70u);
}

// ---------------- helpers ----------------------------------------------------
__device__ __forceinline__ uint32_t smem_u32(const void* p) {
    uint32_t a;
    asm("{ .reg .u64 t; cvta.to.shared.u64 t, %1; cvt.u32.u64 %0, t; }"
        : "=r"(a) : "l"(p));
    return a;
}
__device__ __forceinline__ void ldsm_x4(uint32_t& r0, uint32_t& r1,
                                        uint32_t& r2, uint32_t& r3, uint32_t addr) {
    asm volatile("ldmatrix.sync.aligned.m8n8.x4.shared.b16 {%0,%1,%2,%3}, [%4];"
                 : "=r"(r0), "=r"(r1), "=r"(r2), "=r"(r3) : "r"(addr));
}
__device__ __forceinline__ void mma_f16(float (&c)[4], const uint32_t (&a)[4],
                                        const uint32_t (&b)[2]) {
    asm volatile("mma.sync.aligned.m16n8k16.row.col.f32.f16.f16.f32 "
                 "{%0,%1,%2,%3}, {%4,%5,%6,%7}, {%8,%9}, {%0,%1,%2,%3};"
                 : "+f"(c[0]), "+f"(c[1]), "+f"(c[2]), "+f"(c[3])
                 : "r"(a[0]), "r"(a[1]), "r"(a[2]), "r"(a[3]), "r"(b[0]), "r"(b[1]));
}
// pack two f32 -> f16x2 word: v0 -> bits[15:0], v1 -> bits[31:16]
__device__ __forceinline__ uint32_t pack2h(float v0, float v1) {
    uint32_t r;
    asm("cvt.rn.f16x2.f32 %0, %1, %2;" : "=r"(r) : "f"(v1), "f"(v0));
    return r;
}

__device__ __forceinline__ unsigned encf(float f) {
    unsigned u = __float_as_uint(f);
    return (u & 0x80000000u) ? ~u : (u | 0x80000000u);
}
__device__ __forceinline__ unsigned decf(unsigned u) {
    if (u == 0u) return 0u;
    return (u & 0x80000000u) ? (u & 0x7FFFFFFFu) : ~u;
}

// cp.async staging (512 threads)
__device__ __forceinline__ void stage_async(uint32_t sdst, const unsigned char* g,
                                            int bytes, int tid) {
    for (int i = tid * 16; i < bytes; i += THR * 16)
        asm volatile("cp.async.cg.shared.global [%0], [%1], 16;"
                     :: "r"(sdst + (uint32_t)i), "l"(g + i));
}
#define CP_COMMIT() asm volatile("cp.async.commit_group;" ::: "memory")
#define CP_WAIT0()  asm volatile("cp.async.wait_group 0;" ::: "memory")

// ---------------- BN folding + weight transform (multi-block) ----------------
__global__ void fold_kernel(
    const float* __restrict__ bn0g, const float* __restrict__ bn0b,
    const float* __restrict__ bn0m, const float* __restrict__ bn0v,
    const float* __restrict__ bn1g, const float* __restrict__ bn1b,
    const float* __restrict__ bn1m, const float* __restrict__ bn1v,
    const float* __restrict__ bn2g, const float* __restrict__ bn2b,
    const float* __restrict__ bn2m, const float* __restrict__ bn2v,
    const float* __restrict__ bn3g, const float* __restrict__ bn3b,
    const float* __restrict__ bn3m, const float* __restrict__ bn3v,
    const float* __restrict__ W0, const float* __restrict__ b0,
    const float* __restrict__ W1, const float* __restrict__ b1,
    const float* __restrict__ W2, const float* __restrict__ b2,
    const float* __restrict__ W3)
{
    const int gt = blockIdx.x * 256 + threadIdx.x;
    const int GS = gridDim.x * 256;

    for (int idx = gt; idx < 3 * 64; idx += GS) {
        int i = idx / 64, j = idx % 64;
        float s0 = bn0g[i] * rsqrtf(bn0v[i] + EPSB);
        float s1 = bn1g[j] * rsqrtf(bn1v[j] + EPSB);
        g_W0f[idx] = s0 * W0[idx] * s1;
    }
    for (int j = gt; j < 64; j += GS) {
        float s1 = bn1g[j] * rsqrtf(bn1v[j] + EPSB);
        float sum = 0.f;
        for (int i = 0; i < 3; i++) {
            float s0 = bn0g[i] * rsqrtf(bn0v[i] + EPSB);
            float c0 = bn0b[i] - bn0m[i] * s0;
            sum += c0 * W0[i * 64 + j];
        }
        g_b0f[j] = s1 * (sum + b0[j] - bn1m[j]) + bn1b[j];
    }

    // L1: [128n][64k] fp16, sw128
    for (int idx = gt; idx < 128 * 64; idx += GS) {
        int n = idx >> 6, k = idx & 63;
        float s2 = bn2g[n] * rsqrtf(bn2v[n] + EPSB);
        float w = W1[k * 128 + n] * s2;
        uint32_t off = sw128((uint32_t)(n * 128 + k * 2));
        *(__half*)(g_Wh1 + off) = __float2half_rn(w);
    }
    for (int n = gt; n < 128; n += GS) {
        float s2 = bn2g[n] * rsqrtf(bn2v[n] + EPSB);
        g_b1f[n] = s2 * (b1[n] - bn2m[n]) + bn2b[n];
    }

    // L2: slice (g*2+kc) of 16KB each
    for (int idx = gt; idx < 256 * 128; idx += GS) {
        int n = idx >> 7, k = idx & 127;
        float s3 = bn3g[n] * rsqrtf(bn3v[n] + EPSB);
        float w = W2[k * 256 + n] * s3;
        int g = n >> 7, kc = k >> 6, nl = n & 127, kl = k & 63;
        uint32_t base = (uint32_t)(g * 2 + kc) * 16384u;
        uint32_t off  = sw128((uint32_t)(nl * 128 + kl * 2));
        *(__half*)(g_Wh2 + base + off) = __float2half_rn(w);
    }
    for (int n = gt; n < 256; n += GS) {
        float s3 = bn3g[n] * rsqrtf(bn3v[n] + EPSB);
        g_b2f[n] = s3 * (b2[n] - bn3m[n]) + bn3b[n];
    }

    // L3: slice (kc) of 8KB each: [64n][64k]
    for (int idx = gt; idx < 64 * 256; idx += GS) {
        int n = idx / 256, k = idx % 256;
        float w = W3[k * 64 + n];
        int kc = k >> 6, kl = k & 63;
        uint32_t base = (uint32_t)kc * 8192u;
        uint32_t off  = sw128((uint32_t)(n * 128 + kl * 2));
        *(__half*)(g_Wh3 + base + off) = __float2half_rn(w);
    }
}

// ---------------- output init / decode -------------------------------------
__global__ void init_kernel(uint4* __restrict__ o, int n4) {
    int i = blockIdx.x * 256 + threadIdx.x;
    if (i < n4) o[i] = make_uint4(0u, 0u, 0u, 0u);
}
__global__ void decode_kernel(uint4* __restrict__ o, int n4) {
    int i = blockIdx.x * 256 + threadIdx.x;
    if (i < n4) {
        uint4 v = o[i];
        v.x = decf(v.x); v.y = decf(v.y); v.z = decf(v.z); v.w = decf(v.w);
        o[i] = v;
    }
}

// ---------------- SMEM layout ------------------------------------------------
// 6 act slots (32KB each: [256 rows][128B], single fp16), 2 weight bufs, misc
__host__ __device__ constexpr uint32_t SLOT(int i) { return (uint32_t)i * 32768u; }
static constexpr uint32_t WBUF  = 196608;                // WB0 @ +0, WB1 @ +16384
static constexpr uint32_t MISC  = 229376;
static constexpr uint32_t BIAS1 = MISC;                  // 128 f32
static constexpr uint32_t BIAS2 = MISC + 512;            // 256 f32
static constexpr uint32_t BIAS3 = MISC + 1536;           // 64 f32
static constexpr uint32_t SEGO  = MISC + 1792;           // 256 int
static constexpr uint32_t SMEM_TOTAL = 232448 > (SEGO + 1024) ? (SEGO + 1024) : 232448;

// ---------------- warp GEMM over one 64-K chunk (m32 = 2 m-tiles) ------------
template<int NT>
__device__ __forceinline__ void mma_kchunk1(
    float (&acc)[2][NT][4],
    uint32_t aW,                  // act slot base + wm*32*128
    uint32_t bW,                  // weight slice base + wn*(NT*8)*128
    int lane)
{
    const int rA  = (lane & 7) + ((lane >> 3) & 1) * 8;
    const int kA8 = ((lane >> 4) & 1) * 8;
    const uint32_t xorA = (uint32_t)((rA & 7) << 4);
    const int rB  = (lane & 7) + ((lane >> 4) & 1) * 8;
    const int kB8 = ((lane >> 3) & 1) * 8;
    const uint32_t xorB = (uint32_t)((lane & 7) << 4);

    #pragma unroll
    for (int ks = 0; ks < 4; ks++) {
        const int k0 = ks * 16;
        uint32_t ah[2][4];
        #pragma unroll
        for (int mt = 0; mt < 2; mt++) {
            uint32_t off = (uint32_t)((mt * 16 + rA) * 128)
                         + (((uint32_t)(k0 + kA8) << 1) ^ xorA);
            ldsm_x4(ah[mt][0], ah[mt][1], ah[mt][2], ah[mt][3], aW + off);
        }
        uint32_t bw[NT][2];
        #pragma unroll
        for (int q = 0; q < NT / 2; q++) {
            uint32_t off = (uint32_t)((q * 16 + rB) * 128)
                         + (((uint32_t)(k0 + kB8) << 1) ^ xorB);
            ldsm_x4(bw[2*q][0], bw[2*q][1], bw[2*q+1][0], bw[2*q+1][1], bW + off);
        }
        #pragma unroll
        for (int mt = 0; mt < 2; mt++)
            #pragma unroll
            for (int nt = 0; nt < NT; nt++)
                mma_f16(acc[mt][nt], ah[mt], bw[nt]);
    }
}

// hidden-layer epilogue: acc -> bias -> relu -> fp16 -> act slot (64 cols)
template<int NT>
__device__ __forceinline__ void epi_hidden(
    float (&acc)[2][NT][4], unsigned char* smem, uint32_t outOff,
    const float* sBias, int colBase, int wm, int lane)
{
    const int r0 = lane >> 2;
    #pragma unroll
    for (int mt = 0; mt < 2; mt++) {
        int row1 = wm * 32 + mt * 16 + r0;
        int row2 = row1 + 8;
        #pragma unroll
        for (int nt = 0; nt < NT; nt++) {
            int kl = nt * 8 + (lane & 3) * 2;
            float bi0 = sBias[colBase + kl], bi1 = sBias[colBase + kl + 1];
            {
                float v0 = fmaxf(acc[mt][nt][0] + bi0, 0.f);
                float v1 = fmaxf(acc[mt][nt][1] + bi1, 0.f);
                uint32_t off = (uint32_t)(row1 * 128)
                             + (((uint32_t)kl << 1) ^ ((uint32_t)(row1 & 7) << 4));
                *(uint32_t*)(smem + outOff + off) = pack2h(v0, v1);
            }
            {
                float v0 = fmaxf(acc[mt][nt][2] + bi0, 0.f);
                float v1 = fmaxf(acc[mt][nt][3] + bi1, 0.f);
                uint32_t off = (uint32_t)(row2 * 128)
                             + (((uint32_t)kl << 1) ^ ((uint32_t)(row2 & 7) << 4));
                *(uint32_t*)(smem + outOff + off) = pack2h(v0, v1);
            }
        }
    }
}

// ---------------- fused MLP + scatter ----------------------------------------
__global__ void __launch_bounds__(THR, 1) mlp_kernel(
    const float* __restrict__ pt_fea, const int* __restrict__ pt_ind,
    const float* __restrict__ b3, unsigned* __restrict__ out)
{
    extern __shared__ __align__(1024) unsigned char smem[];
    float* sB1 = (float*)(smem + BIAS1);
    float* sB2 = (float*)(smem + BIAS2);
    float* sB3 = (float*)(smem + BIAS3);
    int*   sSeg = (int*)(smem + SEGO);
    const uint32_t sb = smem_u32(smem);
    const uint32_t WB0 = sb + WBUF, WB1 = sb + WBUF + 16384;

    const int tid = threadIdx.x, wid = tid >> 5, lane = tid & 31;
    const int wm = wid & 7, wn = wid >> 3;   // 8 m-groups (32 rows) x 2 n-groups
    const int blk = blockIdx.x;
    const uint32_t aWm = (uint32_t)(wm * 32 * 128);

    // ---- prologue: kick S0, stage biases/segs, L0 compute ----
    stage_async(WB0, g_Wh1, 16384, tid); CP_COMMIT();

    if (tid < 256) {
        int gp = blk * TIL + tid;
        if (gp < P_) {
            int ix = pt_ind[3 * gp], iy = pt_ind[3 * gp + 1], iz = pt_ind[3 * gp + 2];
            int bb = (gp >= N_) ? 1 : 0;
            sSeg[tid] = ((bb * G_ + iz) * G_ + iy) * G_ + ix;
        } else sSeg[tid] = -1;
    }
    if (tid < 128) sB1[tid] = g_b1f[tid];
    if (tid < 256) sB2[tid] = g_b2f[tid];
    if (tid < 64)  sB3[tid] = b3[tid];

    // L0: 3 -> 64 scalar fp32, fp16 into slot 0 (256 points, 2 threads/pt)
    {
        int p = tid >> 1, j0 = (tid & 1) * 32;
        int gp = blk * TIL + p;
        float x0 = 0.f, x1 = 0.f, x2 = 0.f;
        if (gp < P_) { x0 = pt_fea[gp*3]; x1 = pt_fea[gp*3+1]; x2 = pt_fea[gp*3+2]; }
        #pragma unroll
        for (int j = 0; j < 32; j += 2) {
            int k = j0 + j;
            float v0 = g_b0f[k]   + x0*g_W0f[k]   + x1*g_W0f[64+k]   + x2*g_W0f[128+k];
            float v1 = g_b0f[k+1] + x0*g_W0f[k+1] + x1*g_W0f[64+k+1] + x2*g_W0f[128+k+1];
            v0 = fmaxf(v0, 0.f); v1 = fmaxf(v1, 0.f);
            uint32_t off = sw128((uint32_t)(p * 128 + k * 2));
            *(uint32_t*)(smem + SLOT(0) + off) = pack2h(v0, v1);
        }
    }
    CP_WAIT0();
    __syncthreads();

    // ---- p0: L1 (64->128), in slot0, out slots 1,2; prefetch S1 ----
    stage_async(WB1, g_Wh2, 16384, tid); CP_COMMIT();
    {
        float acc[2][8][4];
        #pragma unroll
        for (int a = 0; a < 2; a++)
            #pragma unroll
            for (int b = 0; b < 8; b++)
                #pragma unroll
                for (int c = 0; c < 4; c++) acc[a][b][c] = 0.f;
        uint32_t bOff = (uint32_t)(wn * 64 * 128);
        mma_kchunk1<8>(acc, sb + SLOT(0) + aWm, WB0 + bOff, lane);
        epi_hidden<8>(acc, smem, SLOT(1 + wn), sB1, wn * 64, wm, lane);
    }
    CP_WAIT0(); __syncthreads();

    // ---- L2 (128->256): g0 over p1,p2 ; g1 over p3,p4 ----
    const int outSlot[4] = {3, 4, 5, 0};
    {
        float acc[2][8][4];
        uint32_t bOff = (uint32_t)(wn * 64 * 128);

        // p1: g0 kc0 on WB1(S1); prefetch S2 -> WB0
        stage_async(WB0, g_Wh2 + 16384, 16384, tid); CP_COMMIT();
        #pragma unroll
        for (int a = 0; a < 2; a++)
            #pragma unroll
            for (int b = 0; b < 8; b++)
                #pragma unroll
                for (int c = 0; c < 4; c++) acc[a][b][c] = 0.f;
        mma_kchunk1<8>(acc, sb + SLOT(1) + aWm, WB1 + bOff, lane);
        CP_WAIT0(); __syncthreads();

        // p2: g0 kc1 on WB0(S2); prefetch S3 -> WB1
        stage_async(WB1, g_Wh2 + 32768, 16384, tid); CP_COMMIT();
        mma_kchunk1<8>(acc, sb + SLOT(2) + aWm, WB0 + bOff, lane);
        epi_hidden<8>(acc, smem, SLOT(outSlot[wn]), sB2, wn * 64, wm, lane);
        CP_WAIT0(); __syncthreads();

        // p3: g1 kc0 on WB1(S3); prefetch S4 -> WB0
        stage_async(WB0, g_Wh2 + 49152, 16384, tid); CP_COMMIT();
        #pragma unroll
        for (int a = 0; a < 2; a++)
            #pragma unroll
            for (int b = 0; b < 8; b++)
                #pragma unroll
                for (int c = 0; c < 4; c++) acc[a][b][c] = 0.f;
        mma_kchunk1<8>(acc, sb + SLOT(1) + aWm, WB1 + bOff, lane);
        CP_WAIT0(); __syncthreads();

        // p4: g1 kc1 on WB0(S4); prefetch S5 -> WB1 (L3 kc0, 8KB)
        stage_async(WB1, g_Wh3, 8192, tid); CP_COMMIT();
        mma_kchunk1<8>(acc, sb + SLOT(2) + aWm, WB0 + bOff, lane);
        epi_hidden<8>(acc, smem, SLOT(outSlot[2 + wn]), sB2, 128 + wn * 64, wm, lane);
        CP_WAIT0(); __syncthreads();
    }

    // ---- L3 (256->64) over p5..p8, then scatter ----
    {
        float acc[2][4][4];
        #pragma unroll
        for (int a = 0; a < 2; a++)
            #pragma unroll
            for (int b = 0; b < 4; b++)
                #pragma unroll
                for (int c = 0; c < 4; c++) acc[a][b][c] = 0.f;
        uint32_t bOff = (uint32_t)(wn * 32 * 128);

        // p5: kc0 on WB1(S5); prefetch S6 -> WB0
        stage_async(WB0, g_Wh3 + 8192, 8192, tid); CP_COMMIT();
        mma_kchunk1<4>(acc, sb + SLOT(3) + aWm, WB1 + bOff, lane);
        CP_WAIT0(); __syncthreads();

        // p6: kc1 on WB0(S6); prefetch S7 -> WB1
        stage_async(WB1, g_Wh3 + 16384, 8192, tid); CP_COMMIT();
        mma_kchunk1<4>(acc, sb + SLOT(4) + aWm, WB0 + bOff, lane);
        CP_WAIT0(); __syncthreads();

        // p7: kc2 on WB1(S7); prefetch S8 -> WB0
        stage_async(WB0, g_Wh3 + 24576, 8192, tid); CP_COMMIT();
        mma_kchunk1<4>(acc, sb + SLOT(5) + aWm, WB1 + bOff, lane);
        CP_WAIT0(); __syncthreads();

        // p8: kc3 on WB0(S8)
        mma_kchunk1<4>(acc, sb + SLOT(0) + aWm, WB0 + bOff, lane);

        // scatter-max
        const int r0 = lane >> 2;
        #pragma unroll
        for (int mt = 0; mt < 2; mt++) {
            int row1 = wm * 32 + mt * 16 + r0;
            int row2 = row1 + 8;
            int seg1 = sSeg[row1], seg2 = sSeg[row2];
            #pragma unroll
            for (int nt = 0; nt < 4; nt++) {
                int col = wn * 32 + nt * 8 + (lane & 3) * 2;
                float bi0 = sB3[col], bi1 = sB3[col + 1];
                if (seg1 >= 0) {
                    unsigned base = (unsigned)seg1 * 64u + (unsigned)col;
                    atomicMax(out + base,     encf(acc[mt][nt][0] + bi0));
                    atomicMax(out + base + 1, encf(acc[mt][nt][1] + bi1));
                }
                if (seg2 >= 0) {
                    unsigned base = (unsigned)seg2 * 64u + (unsigned)col;
                    atomicMax(out + base,     encf(acc[mt][nt][2] + bi0));
                    atomicMax(out + base + 1, encf(acc[mt][nt][3] + bi1));
                }
            }
        }
    }
}

// ---------------- launcher ---------------------------------------------------
extern "C" void kernel_launch(void* const* d_in, const int* in_sizes, int n_in,
                              void* d_out, int out_size)
{
    const float* pt_fea = (const float*)d_in[0];
    const int*   pt_ind = (const int*)  d_in[1];
    const float *bn0g = (const float*)d_in[2],  *bn0b = (const float*)d_in[3],
                *bn0m = (const float*)d_in[4],  *bn0v = (const float*)d_in[5];
    const float *bn1g = (const float*)d_in[6],  *bn1b = (const float*)d_in[7],
                *bn1m = (const float*)d_in[8],  *bn1v = (const float*)d_in[9];
    const float *bn2g = (const float*)d_in[10], *bn2b = (const float*)d_in[11],
                *bn2m = (const float*)d_in[12], *bn2v = (const float*)d_in[13];
    const float *bn3g = (const float*)d_in[14], *bn3b = (const float*)d_in[15],
                *bn3m = (const float*)d_in[16], *bn3v = (const float*)d_in[17];
    const float *W0 = (const float*)d_in[18], *b0 = (const float*)d_in[19];
    const float *W1 = (const float*)d_in[20], *b1 = (const float*)d_in[21];
    const float *W2 = (const float*)d_in[22], *b2 = (const float*)d_in[23];
    const float *W3 = (const float*)d_in[24], *b3 = (const float*)d_in[25];

    cudaFuncSetAttribute(mlp_kernel, cudaFuncAttributeMaxDynamicSharedMemorySize,
                         SMEM_TOTAL);

    fold_kernel<<<64, 256>>>(bn0g, bn0b, bn0m, bn0v, bn1g, bn1b, bn1m, bn1v,
                             bn2g, bn2b, bn2m, bn2v, bn3g, bn3b, bn3m, bn3v,
                             W0, b0, W1, b1, W2, b2, W3);

    const int n4 = NS_ * OUT_ / 4;
    init_kernel<<<(n4 + 255) / 256, 256>>>((uint4*)d_out, n4);

    mlp_kernel<<<NT_CTA, THR, SMEM_TOTAL>>>(pt_fea, pt_ind, b3, (unsigned*)d_out);

    decode_kernel<<<(n4 + 255) / 256, 256>>>((uint4*)d_out, n4);
}